// round 12
// baseline (speedup 1.0000x reference)
#include <cuda_runtime.h>
#include <cuda_bf16.h>
#include <math.h>
#include <stdint.h>

// Problem constants: B=4, L=1024, E=8, D=512, NLAYERS=2
#define Dc 512
#define Gc 4096   // B*L
#define Ec 8
#define MAXEDGE 256
#define KZ 4      // split-K factor for fold GEMMs
#define KLEN 128  // Dc / KZ
#define FOLD_BLOCKS 256

// ---------------- scratch (device globals; no allocations allowed) ----------
__device__ __align__(16) float g_partW[KZ * Dc * Dc];   // fold1 partials
__device__ __align__(16) float g_partb[KZ * Dc];
__device__ __align__(16) float g_partW2[KZ * Dc * Dc];  // fold2 partials
__device__ __align__(16) float g_partb2[KZ * Dc];
__device__ __align__(16) float g_bf[Dc];
__device__ __align__(16) __nv_bfloat16 g_z0h[Gc*Dc];   // hi(z0)       [m][k]
__device__ __align__(16) __nv_bfloat16 g_z0l[Gc*Dc];   // lo residual  [m][k]
__device__ __align__(16) __nv_bfloat16 g_Wfh[Dc*Dc];   // hi(Wf^T)     [n][k]
__device__ __align__(16) __nv_bfloat16 g_Wfl[Dc*Dc];   // lo(Wf^T)     [n][k]
__device__ __align__(16) float g_y[Gc*Dc];

// ---------------- f32x2 packed helpers (FFMA2, for fold GEMMs) --------------
__device__ __forceinline__ unsigned long long bcast2(float x) {
    unsigned long long r;
    asm("mov.b64 %0, {%1, %1};" : "=l"(r) : "f"(x));
    return r;
}
__device__ __forceinline__ void fma2(unsigned long long& d,
                                     unsigned long long a, unsigned long long b) {
    asm("fma.rn.f32x2 %0, %1, %2, %0;" : "+l"(d) : "l"(a), "l"(b));
}
__device__ __forceinline__ float2 unpack2(unsigned long long p) {
    float2 v;
    asm("mov.b64 {%0, %1}, %2;" : "=f"(v.x), "=f"(v.y) : "l"(p));
    return v;
}
__device__ __forceinline__ unsigned short bfu(__nv_bfloat16 h) {
    return *reinterpret_cast<unsigned short*>(&h);
}

// ---------------- 1) fused reduce + fold1 -----------------------------------
// blocks [0, FOLD_BLOCKS): fold1 split-K GEMM  partW = W1 @ W2 (+bias partials)
// blocks [FOLD_BLOCKS, 2304): weighted expert reduce -> z0 split bf16
//   (each reduce block recomputes the w1 mixing vector from hyperedge_index)
__global__ void __launch_bounds__(256)
k_red_fold(const float* __restrict__ X, const int* __restrict__ he, int nnz,
           const float* __restrict__ A, const float* __restrict__ B,
           const float* __restrict__ vsrc,
           float* __restrict__ partW, float* __restrict__ partb) {
    __shared__ float M2s[Ec][Ec];
    __shared__ float degn[Ec];
    __shared__ float dege[MAXEDGE];
    __shared__ float Dinv[Ec];
    __shared__ float Binv[MAXEDGE];
    __shared__ float w1s[Ec];
    __shared__ __align__(16) float As[2][16][68];
    __shared__ __align__(16) float Bs[2][16][68];
    __shared__ float vsm[KLEN];

    const int t = threadIdx.x;

    if (blockIdx.x < FOLD_BLOCKS) {
        // ---------------- fold1 role ----------------
        constexpr int BM = 64, BN = 64, BK = 16, TM = 4, TN = 4;
        const int fid = blockIdx.x;
        const int bx = fid & 7, by = (fid >> 3) & 7, kz = fid >> 6;
        const int brow = by * BM;
        const int bcol = bx * BN;
        const int kbase = kz * KLEN;
        const int tcol = (t % (BN / TN)) * TN;
        const int trow = (t / (BN / TN)) * TM;
        const int ar = t / (BK / 4);
        const int ac = (t % (BK / 4)) * 4;
        const int br = t / (BN / 4);
        const int bc = (t % (BN / 4)) * 4;

        for (int i = t; i < KLEN; i += 256) vsm[i] = vsrc[kbase + i];
        const bool bth = (by == 0) && (t < BN);
        float bacc = 0.f;

        unsigned long long accp[TM / 2][TN];
#pragma unroll
        for (int m = 0; m < TM / 2; m++)
#pragma unroll
            for (int n = 0; n < TN; n++) accp[m][n] = 0ull;

        float4 afrag, bfrag;
        auto ldg = [&](int k0) {
            afrag = *reinterpret_cast<const float4*>(
                &A[(size_t)(brow + ar) * Dc + kbase + k0 + ac]);
            bfrag = *reinterpret_cast<const float4*>(
                &B[(size_t)(kbase + k0 + br) * Dc + bcol + bc]);
        };
        auto sts = [&](int buf) {
            As[buf][ac + 0][ar] = afrag.x;
            As[buf][ac + 1][ar] = afrag.y;
            As[buf][ac + 2][ar] = afrag.z;
            As[buf][ac + 3][ar] = afrag.w;
            *reinterpret_cast<float4*>(&Bs[buf][br][bc]) = bfrag;
        };

        ldg(0);
        sts(0);
        __syncthreads();

        int buf = 0;
        for (int k0 = 0; k0 < KLEN; k0 += BK) {
            const bool has_next = (k0 + BK) < KLEN;
            if (has_next) ldg(k0 + BK);
#pragma unroll
            for (int kk = 0; kk < BK; kk++) {
                unsigned long long rap[TM / 2];
                const unsigned long long* ap =
                    reinterpret_cast<const unsigned long long*>(&As[buf][kk][trow]);
#pragma unroll
                for (int m = 0; m < TM / 2; m++) rap[m] = ap[m];
                float rb[TN];
#pragma unroll
                for (int n = 0; n < TN; n += 4)
                    *reinterpret_cast<float4*>(&rb[n]) =
                        *reinterpret_cast<const float4*>(&Bs[buf][kk][tcol + n]);
                unsigned long long rbb[TN];
#pragma unroll
                for (int n = 0; n < TN; n++) rbb[n] = bcast2(rb[n]);
#pragma unroll
                for (int m = 0; m < TM / 2; m++)
#pragma unroll
                    for (int n = 0; n < TN; n++) fma2(accp[m][n], rap[m], rbb[n]);
            }
            if (bth) {
#pragma unroll 4
                for (int kk = 0; kk < BK; kk++)
                    bacc = fmaf(vsm[k0 + kk], Bs[buf][kk][t], bacc);
            }
            if (has_next) {
                sts(buf ^ 1);
                __syncthreads();
                buf ^= 1;
            }
        }

        if (bth) partb[kz * Dc + bcol + t] = bacc;
        float* W = partW + (size_t)kz * Dc * Dc;
#pragma unroll
        for (int m = 0; m < TM / 2; m++)
#pragma unroll
            for (int n = 0; n < TN; n++) {
                float2 v = unpack2(accp[m][n]);
                W[(size_t)(brow + trow + 2 * m + 0) * Dc + bcol + tcol + n] = v.x;
                W[(size_t)(brow + trow + 2 * m + 1) * Dc + bcol + tcol + n] = v.y;
            }
    } else {
        // ---------------- reduce role (with inline mix) ----------------
        const int* node = he;
        const int* edge = he + nnz;
        if (t < Ec) degn[t] = 0.f;
        for (int e = t; e < MAXEDGE; e += 256) dege[e] = 0.f;
        if (t < Ec * Ec) ((float*)M2s)[t] = 0.f;
        __syncthreads();
        for (int i = t; i < nnz; i += 256) {
            atomicAdd(&degn[node[i]], 1.f);
            atomicAdd(&dege[edge[i]], 1.f);
        }
        __syncthreads();
        if (t < Ec) Dinv[t] = degn[t] > 0.f ? 1.f / degn[t] : 0.f;
        for (int e = t; e < MAXEDGE; e += 256)
            Binv[e] = dege[e] > 0.f ? 1.f / dege[e] : 0.f;
        __syncthreads();
        int total = nnz * nnz;
        for (int p = t; p < total; p += 256) {
            int i = p % nnz, j = p / nnz;
            int ei = edge[i];
            if (ei == edge[j])
                atomicAdd(&M2s[node[j]][node[i]], Dinv[node[j]] * Binv[ei]);
        }
        __syncthreads();
        if (t == 0) {
            float w2[Ec];
            for (int u = 0; u < Ec; u++) {
                float s = 0.f;
                for (int v = 0; v < Ec; v++) s += M2s[v][u];
                w2[u] = s / (float)Ec;
            }
            for (int q = 0; q < Ec; q++) {
                float s = 0.f;
                for (int u = 0; u < Ec; u++) s += M2s[u][q] * w2[u];
                w1s[q] = s;
            }
        }
        __syncthreads();

        int i = (blockIdx.x - FOLD_BLOCKS) * 256 + t;   // < Gc*(Dc/4)
        int g  = i >> 7;
        int d4 = i & 127;
        const float4* xp =
            reinterpret_cast<const float4*>(X) + (size_t)g * Ec * (Dc / 4) + d4;
        float w[Ec];
#pragma unroll
        for (int u = 0; u < Ec; u++) w[u] = w1s[u];
        float4 acc = make_float4(0.f, 0.f, 0.f, 0.f);
#pragma unroll
        for (int u = 0; u < Ec; u++) {
            float4 v = xp[(size_t)u * (Dc / 4)];
            acc.x = fmaf(w[u], v.x, acc.x);
            acc.y = fmaf(w[u], v.y, acc.y);
            acc.z = fmaf(w[u], v.z, acc.z);
            acc.w = fmaf(w[u], v.w, acc.w);
        }
        float a[4] = {acc.x, acc.y, acc.z, acc.w};
        unsigned short h[4], l[4];
#pragma unroll
        for (int j = 0; j < 4; j++) {
            __nv_bfloat16 hb = __float2bfloat16(a[j]);
            __nv_bfloat16 lb = __float2bfloat16(a[j] - __bfloat162float(hb));
            h[j] = bfu(hb);
            l[j] = bfu(lb);
        }
        uint2 uh, ul;
        uh.x = (uint32_t)h[0] | ((uint32_t)h[1] << 16);
        uh.y = (uint32_t)h[2] | ((uint32_t)h[3] << 16);
        ul.x = (uint32_t)l[0] | ((uint32_t)l[1] << 16);
        ul.y = (uint32_t)l[2] | ((uint32_t)l[3] << 16);
        *reinterpret_cast<uint2*>(g_z0h + (size_t)i * 4) = uh;
        *reinterpret_cast<uint2*>(g_z0l + (size_t)i * 4) = ul;
    }
}

// ---------------- 2) fold2': (sum of fold1 partials) @ comb_w ---------------
// A element = ((p0+p1)+p2)+p3 of g_partW (same order as old comb1).
// by==0 blocks also compute b1f inline (s2 via inline mix, partb sums) for the
// fused bias GEMV.
__global__ void __launch_bounds__(256)
k_fold2(const int* __restrict__ he, int nnz,
        const float* __restrict__ Bmat, const float* __restrict__ lin_b,
        const float* __restrict__ pW1, const float* __restrict__ pb1,
        float* __restrict__ partW, float* __restrict__ partb) {
    constexpr int BM = 64, BN = 64, BK = 16, TM = 4, TN = 4;
    __shared__ __align__(16) float As[2][BK][BM + 4];
    __shared__ __align__(16) float Bs[2][BK][BN + 4];
    __shared__ float vsm[KLEN];
    __shared__ float M2s[Ec][Ec];
    __shared__ float degn[Ec];
    __shared__ float dege[MAXEDGE];
    __shared__ float Dinv[Ec];
    __shared__ float Binv[MAXEDGE];
    __shared__ float s2s;

    const int t = threadIdx.x;
    const int brow = blockIdx.y * BM;
    const int bcol = blockIdx.x * BN;
    const int kz   = blockIdx.z;
    const int kbase = kz * KLEN;
    const int tcol = (t % (BN / TN)) * TN;
    const int trow = (t / (BN / TN)) * TM;
    const int ar = t / (BK / 4);
    const int ac = (t % (BK / 4)) * 4;
    const int br = t / (BN / 4);
    const int bc = (t % (BN / 4)) * 4;

    if (blockIdx.y == 0) {
        // inline mix for s2 only
        const int* node = he;
        const int* edge = he + nnz;
        if (t < Ec) degn[t] = 0.f;
        for (int e = t; e < MAXEDGE; e += 256) dege[e] = 0.f;
        if (t < Ec * Ec) ((float*)M2s)[t] = 0.f;
        __syncthreads();
        for (int i = t; i < nnz; i += 256) {
            atomicAdd(&degn[node[i]], 1.f);
            atomicAdd(&dege[edge[i]], 1.f);
        }
        __syncthreads();
        if (t < Ec) Dinv[t] = degn[t] > 0.f ? 1.f / degn[t] : 0.f;
        for (int e = t; e < MAXEDGE; e += 256)
            Binv[e] = dege[e] > 0.f ? 1.f / dege[e] : 0.f;
        __syncthreads();
        int total = nnz * nnz;
        for (int p = t; p < total; p += 256) {
            int i = p % nnz, j = p / nnz;
            int ei = edge[i];
            if (ei == edge[j])
                atomicAdd(&M2s[node[j]][node[i]], Dinv[node[j]] * Binv[ei]);
        }
        __syncthreads();
        if (t == 0) {
            float s2 = 0.f;
            for (int u = 0; u < Ec; u++) {
                float s = 0.f;
                for (int v = 0; v < Ec; v++) s += M2s[v][u];
                s2 += s / (float)Ec;
            }
            s2s = s2;
        }
        __syncthreads();
        for (int i = t; i < KLEN; i += 256) {
            float s = ((pb1[kbase + i] + pb1[Dc + kbase + i])
                       + pb1[2 * Dc + kbase + i]) + pb1[3 * Dc + kbase + i];
            vsm[i] = s2s * s + lin_b[Dc + kbase + i];   // b1f over this K chunk
        }
    }
    const bool bth = (blockIdx.y == 0) && (t < BN);
    float bacc = 0.f;

    unsigned long long accp[TM / 2][TN];
#pragma unroll
    for (int m = 0; m < TM / 2; m++)
#pragma unroll
        for (int n = 0; n < TN; n++) accp[m][n] = 0ull;

    float4 afrag, bfrag;
    auto ldg = [&](int k0) {
        size_t aidx = (size_t)(brow + ar) * Dc + kbase + k0 + ac;
        float4 p0 = *reinterpret_cast<const float4*>(pW1 + aidx);
        float4 p1 = *reinterpret_cast<const float4*>(pW1 + (size_t)Dc * Dc + aidx);
        float4 p2 = *reinterpret_cast<const float4*>(pW1 + 2 * (size_t)Dc * Dc + aidx);
        float4 p3 = *reinterpret_cast<const float4*>(pW1 + 3 * (size_t)Dc * Dc + aidx);
        afrag.x = ((p0.x + p1.x) + p2.x) + p3.x;
        afrag.y = ((p0.y + p1.y) + p2.y) + p3.y;
        afrag.z = ((p0.z + p1.z) + p2.z) + p3.z;
        afrag.w = ((p0.w + p1.w) + p2.w) + p3.w;
        bfrag = *reinterpret_cast<const float4*>(
            &Bmat[(size_t)(kbase + k0 + br) * Dc + bcol + bc]);
    };
    auto sts = [&](int buf) {
        As[buf][ac + 0][ar] = afrag.x;
        As[buf][ac + 1][ar] = afrag.y;
        As[buf][ac + 2][ar] = afrag.z;
        As[buf][ac + 3][ar] = afrag.w;
        *reinterpret_cast<float4*>(&Bs[buf][br][bc]) = bfrag;
    };

    ldg(0);
    sts(0);
    __syncthreads();

    int buf = 0;
    for (int k0 = 0; k0 < KLEN; k0 += BK) {
        const bool has_next = (k0 + BK) < KLEN;
        if (has_next) ldg(k0 + BK);
#pragma unroll
        for (int kk = 0; kk < BK; kk++) {
            unsigned long long rap[TM / 2];
            const unsigned long long* ap =
                reinterpret_cast<const unsigned long long*>(&As[buf][kk][trow]);
#pragma unroll
            for (int m = 0; m < TM / 2; m++) rap[m] = ap[m];
            float rb[TN];
#pragma unroll
            for (int n = 0; n < TN; n += 4)
                *reinterpret_cast<float4*>(&rb[n]) =
                    *reinterpret_cast<const float4*>(&Bs[buf][kk][tcol + n]);
            unsigned long long rbb[TN];
#pragma unroll
            for (int n = 0; n < TN; n++) rbb[n] = bcast2(rb[n]);
#pragma unroll
            for (int m = 0; m < TM / 2; m++)
#pragma unroll
                for (int n = 0; n < TN; n++) fma2(accp[m][n], rap[m], rbb[n]);
        }
        if (bth) {
#pragma unroll 4
            for (int kk = 0; kk < BK; kk++)
                bacc = fmaf(vsm[k0 + kk], Bs[buf][kk][t], bacc);
        }
        if (has_next) {
            sts(buf ^ 1);
            __syncthreads();
            buf ^= 1;
        }
    }

    if (bth) partb[kz * Dc + bcol + t] = bacc;
    float* W = partW + (size_t)kz * Dc * Dc;
#pragma unroll
    for (int m = 0; m < TM / 2; m++)
#pragma unroll
        for (int n = 0; n < TN; n++) {
            float2 v = unpack2(accp[m][n]);
            W[(size_t)(brow + trow + 2 * m + 0) * Dc + bcol + tcol + n] = v.x;
            W[(size_t)(brow + trow + 2 * m + 1) * Dc + bcol + tcol + n] = v.y;
        }
}

// ---------------- 3) combine -> Wf^T split-bf16 + bf ------------------------
__global__ void k_comb2(const float* __restrict__ extra_b) {
    int i = blockIdx.x * blockDim.x + threadIdx.x;   // over Dc*Dc/4
    const float4* p = reinterpret_cast<const float4*>(g_partW2);
    constexpr int STRIDE = Dc * Dc / 4;
    float4 a = p[i], b = p[i + STRIDE], c = p[i + 2 * STRIDE], d = p[i + 3 * STRIDE];
    float r[4];
    r[0] = ((a.x + b.x) + c.x) + d.x;
    r[1] = ((a.y + b.y) + c.y) + d.y;
    r[2] = ((a.z + b.z) + c.z) + d.z;
    r[3] = ((a.w + b.w) + c.w) + d.w;
    int k = i >> 7;            // Wf row (K index of main GEMM)
    int n = (i & 127) * 4;     // Wf col (N index) -> transposed row
#pragma unroll
    for (int j = 0; j < 4; j++) {
        __nv_bfloat16 hb = __float2bfloat16(r[j]);
        __nv_bfloat16 lb = __float2bfloat16(r[j] - __bfloat162float(hb));
        g_Wfh[(size_t)(n + j) * Dc + k] = hb;
        g_Wfl[(size_t)(n + j) * Dc + k] = lb;
    }
    if (i < Dc) {
        float s = ((g_partb2[i] + g_partb2[Dc + i]) + g_partb2[2 * Dc + i])
                  + g_partb2[3 * Dc + i];
        g_bf[i] = s + extra_b[i];
    }
}

// ---------------- 4) main GEMM: mma.sync bf16-split -------------------------
#define MM_BK   16
#define MM_LDK  24
#define MM_TILE (128 * MM_LDK)
#define MM_BUF  (4 * MM_TILE)
#define MM_SMEM (2 * MM_BUF * 2)

__device__ __forceinline__ void mma16816(float* c, uint32_t a0, uint32_t a1,
                                         uint32_t a2, uint32_t a3,
                                         uint32_t b0, uint32_t b1) {
    asm volatile(
        "mma.sync.aligned.m16n8k16.row.col.f32.bf16.bf16.f32 "
        "{%0,%1,%2,%3}, {%4,%5,%6,%7}, {%8,%9}, {%0,%1,%2,%3};"
        : "+f"(c[0]), "+f"(c[1]), "+f"(c[2]), "+f"(c[3])
        : "r"(a0), "r"(a1), "r"(a2), "r"(a3), "r"(b0), "r"(b1));
}

__global__ void __launch_bounds__(256, 1) k_main_mma() {
    extern __shared__ __nv_bfloat16 sm[];
    const int tid  = threadIdx.x;
    const int lane = tid & 31;
    const int wid  = tid >> 5;
    const int wm   = wid >> 1;
    const int wn   = wid & 1;
    const int brow = blockIdx.y * 128;
    const int bcol = blockIdx.x * 128;
    const int g    = lane >> 2;
    const int tg   = lane & 3;

    const int r0 = tid >> 2,  c0 = (tid & 3) * 4;
    const int r1 = r0 + 64;

    float acc[2][8][4];
#pragma unroll
    for (int mf = 0; mf < 2; mf++)
#pragma unroll
        for (int nf = 0; nf < 8; nf++)
#pragma unroll
            for (int q = 0; q < 4; q++) acc[mf][nf][q] = 0.f;

    uint2 pf[8];
    auto ldg = [&](int kb) {
        const __nv_bfloat16* s;
        s = g_z0h + (size_t)(brow + r0) * Dc + kb;  pf[0] = *(const uint2*)(s + c0);
        s = g_z0h + (size_t)(brow + r1) * Dc + kb;  pf[1] = *(const uint2*)(s + c0);
        s = g_z0l + (size_t)(brow + r0) * Dc + kb;  pf[2] = *(const uint2*)(s + c0);
        s = g_z0l + (size_t)(brow + r1) * Dc + kb;  pf[3] = *(const uint2*)(s + c0);
        s = g_Wfh + (size_t)(bcol + r0) * Dc + kb;  pf[4] = *(const uint2*)(s + c0);
        s = g_Wfh + (size_t)(bcol + r1) * Dc + kb;  pf[5] = *(const uint2*)(s + c0);
        s = g_Wfl + (size_t)(bcol + r0) * Dc + kb;  pf[6] = *(const uint2*)(s + c0);
        s = g_Wfl + (size_t)(bcol + r1) * Dc + kb;  pf[7] = *(const uint2*)(s + c0);
    };
    auto sts = [&](int buf) {
        __nv_bfloat16* base = sm + buf * MM_BUF;
#pragma unroll
        for (int a = 0; a < 4; a++) {
            *(uint2*)(base + a * MM_TILE + r0 * MM_LDK + c0) = pf[2 * a + 0];
            *(uint2*)(base + a * MM_TILE + r1 * MM_LDK + c0) = pf[2 * a + 1];
        }
    };

    ldg(0);
    sts(0);
    __syncthreads();

    int buf = 0;
    for (int kt = 0; kt < Dc / MM_BK; kt++) {
        const bool has_next = (kt + 1) < (Dc / MM_BK);
        if (has_next) ldg((kt + 1) * MM_BK);

        const __nv_bfloat16* sAh = sm + buf * MM_BUF + 0 * MM_TILE;
        const __nv_bfloat16* sAl = sm + buf * MM_BUF + 1 * MM_TILE;
        const __nv_bfloat16* sBh = sm + buf * MM_BUF + 2 * MM_TILE;
        const __nv_bfloat16* sBl = sm + buf * MM_BUF + 3 * MM_TILE;

        uint32_t Ah[2][4], Al[2][4];
#pragma unroll
        for (int mf = 0; mf < 2; mf++) {
            const __nv_bfloat16* p = sAh + (wm * 32 + mf * 16 + g) * MM_LDK + tg * 2;
            Ah[mf][0] = *(const uint32_t*)(p);
            Ah[mf][1] = *(const uint32_t*)(p + 8 * MM_LDK);
            Ah[mf][2] = *(const uint32_t*)(p + 8);
            Ah[mf][3] = *(const uint32_t*)(p + 8 * MM_LDK + 8);
            const __nv_bfloat16* q = sAl + (wm * 32 + mf * 16 + g) * MM_LDK + tg * 2;
            Al[mf][0] = *(const uint32_t*)(q);
            Al[mf][1] = *(const uint32_t*)(q + 8 * MM_LDK);
            Al[mf][2] = *(const uint32_t*)(q + 8);
            Al[mf][3] = *(const uint32_t*)(q + 8 * MM_LDK + 8);
        }
        uint32_t Bh[8][2], Bl[8][2];
#pragma unroll
        for (int nf = 0; nf < 8; nf++) {
            const __nv_bfloat16* p = sBh + (wn * 64 + nf * 8 + g) * MM_LDK + tg * 2;
            Bh[nf][0] = *(const uint32_t*)(p);
            Bh[nf][1] = *(const uint32_t*)(p + 8);
            const __nv_bfloat16* q = sBl + (wn * 64 + nf * 8 + g) * MM_LDK + tg * 2;
            Bl[nf][0] = *(const uint32_t*)(q);
            Bl[nf][1] = *(const uint32_t*)(q + 8);
        }
#pragma unroll
        for (int mf = 0; mf < 2; mf++)
#pragma unroll
            for (int nf = 0; nf < 8; nf++) {
                mma16816(acc[mf][nf], Ah[mf][0], Ah[mf][1], Ah[mf][2], Ah[mf][3],
                         Bh[nf][0], Bh[nf][1]);
                mma16816(acc[mf][nf], Ah[mf][0], Ah[mf][1], Ah[mf][2], Ah[mf][3],
                         Bl[nf][0], Bl[nf][1]);
                mma16816(acc[mf][nf], Al[mf][0], Al[mf][1], Al[mf][2], Al[mf][3],
                         Bh[nf][0], Bh[nf][1]);
            }

        if (has_next) {
            sts(buf ^ 1);
            __syncthreads();
            buf ^= 1;
        }
    }

#pragma unroll
    for (int mf = 0; mf < 2; mf++) {
#pragma unroll
        for (int nf = 0; nf < 8; nf++) {
            int mbase = brow + wm * 32 + mf * 16 + g;
            int nbase = bcol + wn * 64 + nf * 8 + tg * 2;
            float b0v = g_bf[nbase], b1v = g_bf[nbase + 1];
            float x0 = acc[mf][nf][0] + b0v;
            float x1 = acc[mf][nf][1] + b1v;
            float x2 = acc[mf][nf][2] + b0v;
            float x3 = acc[mf][nf][3] + b1v;
            float2 lo, hi;
            lo.x = 0.5f * x0 * (1.f + erff(x0 * 0.70710678118654752f));
            lo.y = 0.5f * x1 * (1.f + erff(x1 * 0.70710678118654752f));
            hi.x = 0.5f * x2 * (1.f + erff(x2 * 0.70710678118654752f));
            hi.y = 0.5f * x3 * (1.f + erff(x3 * 0.70710678118654752f));
            *reinterpret_cast<float2*>(g_y + (size_t)mbase * Dc + nbase) = lo;
            *reinterpret_cast<float2*>(g_y + (size_t)(mbase + 8) * Dc + nbase) = hi;
        }
    }
}

// ---------------- 5) LayerNorm over D=512 -----------------------------------
__global__ void k_ln(const float* __restrict__ Y, const float* __restrict__ gam,
                     const float* __restrict__ bet, float* __restrict__ out) {
    int row = blockIdx.x;
    const float* y = Y + (size_t)row * Dc;
    int t = threadIdx.x;
    float v[4];
    float s = 0.f;
#pragma unroll
    for (int i = 0; i < 4; i++) { v[i] = y[t + i * 128]; s += v[i]; }
    __shared__ float red[4];
#pragma unroll
    for (int o = 16; o; o >>= 1) s += __shfl_xor_sync(0xffffffffu, s, o);
    if ((t & 31) == 0) red[t >> 5] = s;
    __syncthreads();
    float mu = (red[0] + red[1] + red[2] + red[3]) * (1.f / Dc);
    __syncthreads();
    float d2 = 0.f;
#pragma unroll
    for (int i = 0; i < 4; i++) { float d = v[i] - mu; d2 += d * d; }
#pragma unroll
    for (int o = 16; o; o >>= 1) d2 += __shfl_xor_sync(0xffffffffu, d2, o);
    if ((t & 31) == 0) red[t >> 5] = d2;
    __syncthreads();
    float var = (red[0] + red[1] + red[2] + red[3]) * (1.f / Dc);
    float rs = rsqrtf(var + 1e-5f);
#pragma unroll
    for (int i = 0; i < 4; i++) {
        int c = t + i * 128;
        out[(size_t)row * Dc + c] = (v[i] - mu) * rs * gam[c] + bet[c];
    }
}

// ---------------- launch -----------------------------------------------------
extern "C" void kernel_launch(void* const* d_in, const int* in_sizes, int n_in,
                              void* d_out, int out_size) {
    const float* x      = (const float*)d_in[0];
    const int*   he     = (const int*)  d_in[1];
    const float* lin_w  = (const float*)d_in[2];
    const float* lin_b  = (const float*)d_in[3];
    const float* comb_w = (const float*)d_in[4];
    const float* comb_b = (const float*)d_in[5];
    const float* ln_g   = (const float*)d_in[6];
    const float* ln_b   = (const float*)d_in[7];
    float* out = (float*)d_out;
    const int nnz = in_sizes[1] / 2;

    float *p_y, *p_partW, *p_partb, *p_partW2, *p_partb2;
    cudaGetSymbolAddress((void**)&p_y,      g_y);
    cudaGetSymbolAddress((void**)&p_partW,  g_partW);
    cudaGetSymbolAddress((void**)&p_partb,  g_partb);
    cudaGetSymbolAddress((void**)&p_partW2, g_partW2);
    cudaGetSymbolAddress((void**)&p_partb2, g_partb2);

    cudaFuncSetAttribute(k_main_mma,
                         cudaFuncAttributeMaxDynamicSharedMemorySize, MM_SMEM);

    // 1) fused: fold1 (blocks 0-255) + weighted expert reduce (blocks 256-2303)
    {
        int grid = FOLD_BLOCKS + Gc * (Dc / 4) / 256;   // 256 + 2048
        k_red_fold<<<grid, 256>>>(x, he, nnz, lin_w, lin_w + Dc * Dc, lin_b,
                                  p_partW, p_partb);
    }

    // 2) fold2': (sum partW) @ comb_w ; bias GEMV on inline-computed b1f
    {
        dim3 grid(Dc / 64, Dc / 64, KZ);
        k_fold2<<<grid, 256>>>(he, nnz, comb_w, lin_b, p_partW, p_partb,
                               p_partW2, p_partb2);
    }

    // 3) combine -> Wf^T split-bf16 + bf
    k_comb2<<<Dc * Dc / 4 / 256, 256>>>(comb_b);

    // 4) main GEMM on tensor cores (mma.sync): y = gelu(z0 @ Wf + bf)
    {
        dim3 grid(Dc / 128, Gc / 128);   // (4, 32) = 128 CTAs = 1 wave
        k_main_mma<<<grid, 256, MM_SMEM>>>();
    }

    // 5) LayerNorm -> output
    k_ln<<<Gc, 128>>>(p_y, ln_g, ln_b, out);
}

// round 14
// speedup vs baseline: 1.0383x; 1.0383x over previous
#include <cuda_runtime.h>
#include <cuda_bf16.h>
#include <math.h>
#include <stdint.h>

// Problem constants: B=4, L=1024, E=8, D=512, NLAYERS=2
#define Dc 512
#define Gc 4096   // B*L
#define Ec 8
#define MAXEDGE 256
#define KZ 4      // split-K factor for fold GEMMs
#define KLEN 128  // Dc / KZ
#define FOLD_BLOCKS 256

// ---------------- scratch (device globals; no allocations allowed) ----------
__device__ __align__(16) float g_partW[KZ * Dc * Dc];   // fold1 partials
__device__ __align__(16) float g_partb[KZ * Dc];
__device__ __align__(16) float g_partW2[KZ * Dc * Dc];  // fold2 partials
__device__ __align__(16) float g_partb2[KZ * Dc];
__device__ __align__(16) float g_bf[Dc];
__device__ __align__(16) __nv_bfloat16 g_z0h[Gc*Dc];   // hi(z0)       [m][k]
__device__ __align__(16) __nv_bfloat16 g_z0l[Gc*Dc];   // lo residual  [m][k]
__device__ __align__(16) __nv_bfloat16 g_Wfh[Dc*Dc];   // hi(Wf^T)     [n][k]
__device__ __align__(16) __nv_bfloat16 g_Wfl[Dc*Dc];   // lo(Wf^T)     [n][k]
__device__ __align__(16) float g_y[Gc*Dc];

// ---------------- f32x2 packed helpers (FFMA2, for fold GEMMs) --------------
__device__ __forceinline__ unsigned long long bcast2(float x) {
    unsigned long long r;
    asm("mov.b64 %0, {%1, %1};" : "=l"(r) : "f"(x));
    return r;
}
__device__ __forceinline__ void fma2(unsigned long long& d,
                                     unsigned long long a, unsigned long long b) {
    asm("fma.rn.f32x2 %0, %1, %2, %0;" : "+l"(d) : "l"(a), "l"(b));
}
__device__ __forceinline__ float2 unpack2(unsigned long long p) {
    float2 v;
    asm("mov.b64 {%0, %1}, %2;" : "=f"(v.x), "=f"(v.y) : "l"(p));
    return v;
}
__device__ __forceinline__ unsigned short bfu(__nv_bfloat16 h) {
    return *reinterpret_cast<unsigned short*>(&h);
}

// ---------------- 1) fused reduce + fold1 -----------------------------------
__global__ void __launch_bounds__(256)
k_red_fold(const float* __restrict__ X, const int* __restrict__ he, int nnz,
           const float* __restrict__ A, const float* __restrict__ B,
           const float* __restrict__ vsrc,
           float* __restrict__ partW, float* __restrict__ partb) {
    __shared__ float M2s[Ec][Ec];
    __shared__ float degn[Ec];
    __shared__ float dege[MAXEDGE];
    __shared__ float Dinv[Ec];
    __shared__ float Binv[MAXEDGE];
    __shared__ float w1s[Ec];
    __shared__ __align__(16) float As[2][16][68];
    __shared__ __align__(16) float Bs[2][16][68];
    __shared__ float vsm[KLEN];

    const int t = threadIdx.x;

    if (blockIdx.x < FOLD_BLOCKS) {
        constexpr int BM = 64, BN = 64, BK = 16, TM = 4, TN = 4;
        const int fid = blockIdx.x;
        const int bx = fid & 7, by = (fid >> 3) & 7, kz = fid >> 6;
        const int brow = by * BM;
        const int bcol = bx * BN;
        const int kbase = kz * KLEN;
        const int tcol = (t % (BN / TN)) * TN;
        const int trow = (t / (BN / TN)) * TM;
        const int ar = t / (BK / 4);
        const int ac = (t % (BK / 4)) * 4;
        const int br = t / (BN / 4);
        const int bc = (t % (BN / 4)) * 4;

        for (int i = t; i < KLEN; i += 256) vsm[i] = vsrc[kbase + i];
        const bool bth = (by == 0) && (t < BN);
        float bacc = 0.f;

        unsigned long long accp[TM / 2][TN];
#pragma unroll
        for (int m = 0; m < TM / 2; m++)
#pragma unroll
            for (int n = 0; n < TN; n++) accp[m][n] = 0ull;

        float4 afrag, bfrag;
        auto ldg = [&](int k0) {
            afrag = *reinterpret_cast<const float4*>(
                &A[(size_t)(brow + ar) * Dc + kbase + k0 + ac]);
            bfrag = *reinterpret_cast<const float4*>(
                &B[(size_t)(kbase + k0 + br) * Dc + bcol + bc]);
        };
        auto sts = [&](int buf) {
            As[buf][ac + 0][ar] = afrag.x;
            As[buf][ac + 1][ar] = afrag.y;
            As[buf][ac + 2][ar] = afrag.z;
            As[buf][ac + 3][ar] = afrag.w;
            *reinterpret_cast<float4*>(&Bs[buf][br][bc]) = bfrag;
        };

        ldg(0);
        sts(0);
        __syncthreads();

        int buf = 0;
        for (int k0 = 0; k0 < KLEN; k0 += BK) {
            const bool has_next = (k0 + BK) < KLEN;
            if (has_next) ldg(k0 + BK);
#pragma unroll
            for (int kk = 0; kk < BK; kk++) {
                unsigned long long rap[TM / 2];
                const unsigned long long* ap =
                    reinterpret_cast<const unsigned long long*>(&As[buf][kk][trow]);
#pragma unroll
                for (int m = 0; m < TM / 2; m++) rap[m] = ap[m];
                float rb[TN];
#pragma unroll
                for (int n = 0; n < TN; n += 4)
                    *reinterpret_cast<float4*>(&rb[n]) =
                        *reinterpret_cast<const float4*>(&Bs[buf][kk][tcol + n]);
                unsigned long long rbb[TN];
#pragma unroll
                for (int n = 0; n < TN; n++) rbb[n] = bcast2(rb[n]);
#pragma unroll
                for (int m = 0; m < TM / 2; m++)
#pragma unroll
                    for (int n = 0; n < TN; n++) fma2(accp[m][n], rap[m], rbb[n]);
            }
            if (bth) {
#pragma unroll 4
                for (int kk = 0; kk < BK; kk++)
                    bacc = fmaf(vsm[k0 + kk], Bs[buf][kk][t], bacc);
            }
            if (has_next) {
                sts(buf ^ 1);
                __syncthreads();
                buf ^= 1;
            }
        }

        if (bth) partb[kz * Dc + bcol + t] = bacc;
        float* W = partW + (size_t)kz * Dc * Dc;
#pragma unroll
        for (int m = 0; m < TM / 2; m++)
#pragma unroll
            for (int n = 0; n < TN; n++) {
                float2 v = unpack2(accp[m][n]);
                W[(size_t)(brow + trow + 2 * m + 0) * Dc + bcol + tcol + n] = v.x;
                W[(size_t)(brow + trow + 2 * m + 1) * Dc + bcol + tcol + n] = v.y;
            }
    } else {
        const int* node = he;
        const int* edge = he + nnz;
        if (t < Ec) degn[t] = 0.f;
        for (int e = t; e < MAXEDGE; e += 256) dege[e] = 0.f;
        if (t < Ec * Ec) ((float*)M2s)[t] = 0.f;
        __syncthreads();
        for (int i = t; i < nnz; i += 256) {
            atomicAdd(&degn[node[i]], 1.f);
            atomicAdd(&dege[edge[i]], 1.f);
        }
        __syncthreads();
        if (t < Ec) Dinv[t] = degn[t] > 0.f ? 1.f / degn[t] : 0.f;
        for (int e = t; e < MAXEDGE; e += 256)
            Binv[e] = dege[e] > 0.f ? 1.f / dege[e] : 0.f;
        __syncthreads();
        int total = nnz * nnz;
        for (int p = t; p < total; p += 256) {
            int i = p % nnz, j = p / nnz;
            int ei = edge[i];
            if (ei == edge[j])
                atomicAdd(&M2s[node[j]][node[i]], Dinv[node[j]] * Binv[ei]);
        }
        __syncthreads();
        if (t == 0) {
            float w2[Ec];
            for (int u = 0; u < Ec; u++) {
                float s = 0.f;
                for (int v = 0; v < Ec; v++) s += M2s[v][u];
                w2[u] = s / (float)Ec;
            }
            for (int q = 0; q < Ec; q++) {
                float s = 0.f;
                for (int u = 0; u < Ec; u++) s += M2s[u][q] * w2[u];
                w1s[q] = s;
            }
        }
        __syncthreads();

        int i = (blockIdx.x - FOLD_BLOCKS) * 256 + t;
        int g  = i >> 7;
        int d4 = i & 127;
        const float4* xp =
            reinterpret_cast<const float4*>(X) + (size_t)g * Ec * (Dc / 4) + d4;
        float w[Ec];
#pragma unroll
        for (int u = 0; u < Ec; u++) w[u] = w1s[u];
        float4 acc = make_float4(0.f, 0.f, 0.f, 0.f);
#pragma unroll
        for (int u = 0; u < Ec; u++) {
            float4 v = xp[(size_t)u * (Dc / 4)];
            acc.x = fmaf(w[u], v.x, acc.x);
            acc.y = fmaf(w[u], v.y, acc.y);
            acc.z = fmaf(w[u], v.z, acc.z);
            acc.w = fmaf(w[u], v.w, acc.w);
        }
        float a[4] = {acc.x, acc.y, acc.z, acc.w};
        unsigned short h[4], l[4];
#pragma unroll
        for (int j = 0; j < 4; j++) {
            __nv_bfloat16 hb = __float2bfloat16(a[j]);
            __nv_bfloat16 lb = __float2bfloat16(a[j] - __bfloat162float(hb));
            h[j] = bfu(hb);
            l[j] = bfu(lb);
        }
        uint2 uh, ul;
        uh.x = (uint32_t)h[0] | ((uint32_t)h[1] << 16);
        uh.y = (uint32_t)h[2] | ((uint32_t)h[3] << 16);
        ul.x = (uint32_t)l[0] | ((uint32_t)l[1] << 16);
        ul.y = (uint32_t)l[2] | ((uint32_t)l[3] << 16);
        *reinterpret_cast<uint2*>(g_z0h + (size_t)i * 4) = uh;
        *reinterpret_cast<uint2*>(g_z0l + (size_t)i * 4) = ul;
    }
}

// ---------------- 2) fold2': (sum of fold1 partials) @ comb_w ---------------
__global__ void __launch_bounds__(256)
k_fold2(const int* __restrict__ he, int nnz,
        const float* __restrict__ Bmat, const float* __restrict__ lin_b,
        const float* __restrict__ pW1, const float* __restrict__ pb1,
        float* __restrict__ partW, float* __restrict__ partb) {
    constexpr int BM = 64, BN = 64, BK = 16, TM = 4, TN = 4;
    __shared__ __align__(16) float As[2][BK][BM + 4];
    __shared__ __align__(16) float Bs[2][BK][BN + 4];
    __shared__ float vsm[KLEN];
    __shared__ float M2s[Ec][Ec];
    __shared__ float degn[Ec];
    __shared__ float dege[MAXEDGE];
    __shared__ float Dinv[Ec];
    __shared__ float Binv[MAXEDGE];
    __shared__ float s2s;

    const int t = threadIdx.x;
    const int brow = blockIdx.y * BM;
    const int bcol = blockIdx.x * BN;
    const int kz   = blockIdx.z;
    const int kbase = kz * KLEN;
    const int tcol = (t % (BN / TN)) * TN;
    const int trow = (t / (BN / TN)) * TM;
    const int ar = t / (BK / 4);
    const int ac = (t % (BK / 4)) * 4;
    const int br = t / (BN / 4);
    const int bc = (t % (BN / 4)) * 4;

    if (blockIdx.y == 0) {
        const int* node = he;
        const int* edge = he + nnz;
        if (t < Ec) degn[t] = 0.f;
        for (int e = t; e < MAXEDGE; e += 256) dege[e] = 0.f;
        if (t < Ec * Ec) ((float*)M2s)[t] = 0.f;
        __syncthreads();
        for (int i = t; i < nnz; i += 256) {
            atomicAdd(&degn[node[i]], 1.f);
            atomicAdd(&dege[edge[i]], 1.f);
        }
        __syncthreads();
        if (t < Ec) Dinv[t] = degn[t] > 0.f ? 1.f / degn[t] : 0.f;
        for (int e = t; e < MAXEDGE; e += 256)
            Binv[e] = dege[e] > 0.f ? 1.f / dege[e] : 0.f;
        __syncthreads();
        int total = nnz * nnz;
        for (int p = t; p < total; p += 256) {
            int i = p % nnz, j = p / nnz;
            int ei = edge[i];
            if (ei == edge[j])
                atomicAdd(&M2s[node[j]][node[i]], Dinv[node[j]] * Binv[ei]);
        }
        __syncthreads();
        if (t == 0) {
            float s2 = 0.f;
            for (int u = 0; u < Ec; u++) {
                float s = 0.f;
                for (int v = 0; v < Ec; v++) s += M2s[v][u];
                s2 += s / (float)Ec;
            }
            s2s = s2;
        }
        __syncthreads();
        for (int i = t; i < KLEN; i += 256) {
            float s = ((pb1[kbase + i] + pb1[Dc + kbase + i])
                       + pb1[2 * Dc + kbase + i]) + pb1[3 * Dc + kbase + i];
            vsm[i] = s2s * s + lin_b[Dc + kbase + i];
        }
    }
    const bool bth = (blockIdx.y == 0) && (t < BN);
    float bacc = 0.f;

    unsigned long long accp[TM / 2][TN];
#pragma unroll
    for (int m = 0; m < TM / 2; m++)
#pragma unroll
        for (int n = 0; n < TN; n++) accp[m][n] = 0ull;

    float4 afrag, bfrag;
    auto ldg = [&](int k0) {
        size_t aidx = (size_t)(brow + ar) * Dc + kbase + k0 + ac;
        float4 p0 = *reinterpret_cast<const float4*>(pW1 + aidx);
        float4 p1 = *reinterpret_cast<const float4*>(pW1 + (size_t)Dc * Dc + aidx);
        float4 p2 = *reinterpret_cast<const float4*>(pW1 + 2 * (size_t)Dc * Dc + aidx);
        float4 p3 = *reinterpret_cast<const float4*>(pW1 + 3 * (size_t)Dc * Dc + aidx);
        afrag.x = ((p0.x + p1.x) + p2.x) + p3.x;
        afrag.y = ((p0.y + p1.y) + p2.y) + p3.y;
        afrag.z = ((p0.z + p1.z) + p2.z) + p3.z;
        afrag.w = ((p0.w + p1.w) + p2.w) + p3.w;
        bfrag = *reinterpret_cast<const float4*>(
            &Bmat[(size_t)(kbase + k0 + br) * Dc + bcol + bc]);
    };
    auto sts = [&](int buf) {
        As[buf][ac + 0][ar] = afrag.x;
        As[buf][ac + 1][ar] = afrag.y;
        As[buf][ac + 2][ar] = afrag.z;
        As[buf][ac + 3][ar] = afrag.w;
        *reinterpret_cast<float4*>(&Bs[buf][br][bc]) = bfrag;
    };

    ldg(0);
    sts(0);
    __syncthreads();

    int buf = 0;
    for (int k0 = 0; k0 < KLEN; k0 += BK) {
        const bool has_next = (k0 + BK) < KLEN;
        if (has_next) ldg(k0 + BK);
#pragma unroll
        for (int kk = 0; kk < BK; kk++) {
            unsigned long long rap[TM / 2];
            const unsigned long long* ap =
                reinterpret_cast<const unsigned long long*>(&As[buf][kk][trow]);
#pragma unroll
            for (int m = 0; m < TM / 2; m++) rap[m] = ap[m];
            float rb[TN];
#pragma unroll
            for (int n = 0; n < TN; n += 4)
                *reinterpret_cast<float4*>(&rb[n]) =
                    *reinterpret_cast<const float4*>(&Bs[buf][kk][tcol + n]);
            unsigned long long rbb[TN];
#pragma unroll
            for (int n = 0; n < TN; n++) rbb[n] = bcast2(rb[n]);
#pragma unroll
            for (int m = 0; m < TM / 2; m++)
#pragma unroll
                for (int n = 0; n < TN; n++) fma2(accp[m][n], rap[m], rbb[n]);
        }
        if (bth) {
#pragma unroll 4
            for (int kk = 0; kk < BK; kk++)
                bacc = fmaf(vsm[k0 + kk], Bs[buf][kk][t], bacc);
        }
        if (has_next) {
            sts(buf ^ 1);
            __syncthreads();
            buf ^= 1;
        }
    }

    if (bth) partb[kz * Dc + bcol + t] = bacc;
    float* W = partW + (size_t)kz * Dc * Dc;
#pragma unroll
    for (int m = 0; m < TM / 2; m++)
#pragma unroll
        for (int n = 0; n < TN; n++) {
            float2 v = unpack2(accp[m][n]);
            W[(size_t)(brow + trow + 2 * m + 0) * Dc + bcol + tcol + n] = v.x;
            W[(size_t)(brow + trow + 2 * m + 1) * Dc + bcol + tcol + n] = v.y;
        }
}

// ---------------- 3) combine -> Wf^T split-bf16 + bf ------------------------
__global__ void k_comb2(const float* __restrict__ extra_b) {
    int i = blockIdx.x * blockDim.x + threadIdx.x;
    const float4* p = reinterpret_cast<const float4*>(g_partW2);
    constexpr int STRIDE = Dc * Dc / 4;
    float4 a = p[i], b = p[i + STRIDE], c = p[i + 2 * STRIDE], d = p[i + 3 * STRIDE];
    float r[4];
    r[0] = ((a.x + b.x) + c.x) + d.x;
    r[1] = ((a.y + b.y) + c.y) + d.y;
    r[2] = ((a.z + b.z) + c.z) + d.z;
    r[3] = ((a.w + b.w) + c.w) + d.w;
    int k = i >> 7;
    int n = (i & 127) * 4;
#pragma unroll
    for (int j = 0; j < 4; j++) {
        __nv_bfloat16 hb = __float2bfloat16(r[j]);
        __nv_bfloat16 lb = __float2bfloat16(r[j] - __bfloat162float(hb));
        g_Wfh[(size_t)(n + j) * Dc + k] = hb;
        g_Wfl[(size_t)(n + j) * Dc + k] = lb;
    }
    if (i < Dc) {
        float s = ((g_partb2[i] + g_partb2[Dc + i]) + g_partb2[2 * Dc + i])
                  + g_partb2[3 * Dc + i];
        g_bf[i] = s + extra_b[i];
    }
}

// ---------------- 4) main GEMM: mma.sync bf16-split + ldmatrix --------------
// 512 threads, 16 warps as 4(m) x 4(n), warp tile 32x32, BK=16, double buffer.
#define MM_BK   16
#define MM_LDK  24                      // padded row (bf16) -> 48B, ldmatrix conflict-free
#define MM_TILE (128 * MM_LDK)
#define MM_BUF  (4 * MM_TILE)           // Ah, Al, Bh, Bl
#define MM_SMEM (2 * MM_BUF * 2)        // 49152 bytes

__device__ __forceinline__ void mma16816(float* c, uint32_t a0, uint32_t a1,
                                         uint32_t a2, uint32_t a3,
                                         uint32_t b0, uint32_t b1) {
    asm volatile(
        "mma.sync.aligned.m16n8k16.row.col.f32.bf16.bf16.f32 "
        "{%0,%1,%2,%3}, {%4,%5,%6,%7}, {%8,%9}, {%0,%1,%2,%3};"
        : "+f"(c[0]), "+f"(c[1]), "+f"(c[2]), "+f"(c[3])
        : "r"(a0), "r"(a1), "r"(a2), "r"(a3), "r"(b0), "r"(b1));
}

__device__ __forceinline__ void ldm_x4(uint32_t& r0, uint32_t& r1,
                                       uint32_t& r2, uint32_t& r3, uint32_t addr) {
    asm volatile(
        "ldmatrix.sync.aligned.m8n8.x4.shared.b16 {%0,%1,%2,%3}, [%4];"
        : "=r"(r0), "=r"(r1), "=r"(r2), "=r"(r3) : "r"(addr));
}

__global__ void __launch_bounds__(512, 1) k_main_mma() {
    extern __shared__ __nv_bfloat16 sm[];
    const int tid  = threadIdx.x;
    const int lane = tid & 31;
    const int wid  = tid >> 5;          // 0..15
    const int wm   = wid >> 2;          // m offset wm*32
    const int wn   = wid & 3;           // n offset wn*32
    const int brow = blockIdx.y * 128;
    const int bcol = blockIdx.x * 128;
    const int g    = lane >> 2;
    const int tg   = lane & 3;

    // global->smem staging coords (512 threads: 1 uint2 per tile per thread)
    const int r0 = tid >> 2, c0 = (tid & 3) * 4;

    // ldmatrix lane address components
    const int sel = lane >> 3;          // 0..3 (8x8 matrix index)
    const int rim = lane & 7;           // row within matrix
    // A matrices: sel0 rows+0 k0 | sel1 rows+8 k0 | sel2 rows+0 k8 | sel3 rows+8 k8
    const int a_row = (sel & 1) * 8 + rim;
    const int a_k   = (sel >> 1) * 8;
    // B matrices: sel0 n+0 k0 | sel1 n+0 k8 | sel2 n+8 k0 | sel3 n+8 k8
    const int b_row = (sel >> 1) * 8 + rim;
    const int b_k   = (sel & 1) * 8;

    float acc[2][4][4];
#pragma unroll
    for (int mf = 0; mf < 2; mf++)
#pragma unroll
        for (int nf = 0; nf < 4; nf++)
#pragma unroll
            for (int q = 0; q < 4; q++) acc[mf][nf][q] = 0.f;

    uint2 pf[4];
    auto ldg = [&](int kb) {
        pf[0] = *(const uint2*)(g_z0h + (size_t)(brow + r0) * Dc + kb + c0);
        pf[1] = *(const uint2*)(g_z0l + (size_t)(brow + r0) * Dc + kb + c0);
        pf[2] = *(const uint2*)(g_Wfh + (size_t)(bcol + r0) * Dc + kb + c0);
        pf[3] = *(const uint2*)(g_Wfl + (size_t)(bcol + r0) * Dc + kb + c0);
    };
    auto sts = [&](int buf) {
        __nv_bfloat16* base = sm + buf * MM_BUF + r0 * MM_LDK + c0;
#pragma unroll
        for (int a = 0; a < 4; a++)
            *(uint2*)(base + a * MM_TILE) = pf[a];
    };

    ldg(0);
    sts(0);
    __syncthreads();

    int buf = 0;
    for (int kt = 0; kt < Dc / MM_BK; kt++) {
        const bool has_next = (kt + 1) < (Dc / MM_BK);
        if (has_next) ldg((kt + 1) * MM_BK);

        const __nv_bfloat16* base = sm + buf * MM_BUF;
        // A fragments via ldmatrix (mf = 0,1; hi and lo tiles)
        uint32_t Ah[2][4], Al[2][4];
#pragma unroll
        for (int mf = 0; mf < 2; mf++) {
            uint32_t ah = (uint32_t)__cvta_generic_to_shared(
                base + 0 * MM_TILE + (wm * 32 + mf * 16 + a_row) * MM_LDK + a_k);
            ldm_x4(Ah[mf][0], Ah[mf][1], Ah[mf][2], Ah[mf][3], ah);
            uint32_t al = (uint32_t)__cvta_generic_to_shared(
                base + 1 * MM_TILE + (wm * 32 + mf * 16 + a_row) * MM_LDK + a_k);
            ldm_x4(Al[mf][0], Al[mf][1], Al[mf][2], Al[mf][3], al);
        }
        // B fragments via ldmatrix (nf2 = 0,1 covering n 0..15 / 16..31)
        // x4 regs: r0 = b0 (n+0..7), r1 = b1 (n+0..7), r2 = b0 (n+8..15), r3 = b1
        uint32_t Bh[4][2], Bl[4][2];
#pragma unroll
        for (int nf2 = 0; nf2 < 2; nf2++) {
            uint32_t bh = (uint32_t)__cvta_generic_to_shared(
                base + 2 * MM_TILE + (wn * 32 + nf2 * 16 + b_row) * MM_LDK + b_k);
            ldm_x4(Bh[nf2 * 2][0], Bh[nf2 * 2][1],
                   Bh[nf2 * 2 + 1][0], Bh[nf2 * 2 + 1][1], bh);
            uint32_t bl = (uint32_t)__cvta_generic_to_shared(
                base + 3 * MM_TILE + (wn * 32 + nf2 * 16 + b_row) * MM_LDK + b_k);
            ldm_x4(Bl[nf2 * 2][0], Bl[nf2 * 2][1],
                   Bl[nf2 * 2 + 1][0], Bl[nf2 * 2 + 1][1], bl);
        }
#pragma unroll
        for (int mf = 0; mf < 2; mf++)
#pragma unroll
            for (int nf = 0; nf < 4; nf++) {
                mma16816(acc[mf][nf], Ah[mf][0], Ah[mf][1], Ah[mf][2], Ah[mf][3],
                         Bh[nf][0], Bh[nf][1]);
                mma16816(acc[mf][nf], Ah[mf][0], Ah[mf][1], Ah[mf][2], Ah[mf][3],
                         Bl[nf][0], Bl[nf][1]);
                mma16816(acc[mf][nf], Al[mf][0], Al[mf][1], Al[mf][2], Al[mf][3],
                         Bh[nf][0], Bh[nf][1]);
            }

        if (has_next) {
            sts(buf ^ 1);
            __syncthreads();
            buf ^= 1;
        }
    }

    // epilogue: bias + exact GELU
#pragma unroll
    for (int mf = 0; mf < 2; mf++) {
#pragma unroll
        for (int nf = 0; nf < 4; nf++) {
            int mbase = brow + wm * 32 + mf * 16 + g;
            int nbase = bcol + wn * 32 + nf * 8 + tg * 2;
            float b0v = g_bf[nbase], b1v = g_bf[nbase + 1];
            float x0 = acc[mf][nf][0] + b0v;
            float x1 = acc[mf][nf][1] + b1v;
            float x2 = acc[mf][nf][2] + b0v;
            float x3 = acc[mf][nf][3] + b1v;
            float2 lo, hi;
            lo.x = 0.5f * x0 * (1.f + erff(x0 * 0.70710678118654752f));
            lo.y = 0.5f * x1 * (1.f + erff(x1 * 0.70710678118654752f));
            hi.x = 0.5f * x2 * (1.f + erff(x2 * 0.70710678118654752f));
            hi.y = 0.5f * x3 * (1.f + erff(x3 * 0.70710678118654752f));
            *reinterpret_cast<float2*>(g_y + (size_t)mbase * Dc + nbase) = lo;
            *reinterpret_cast<float2*>(g_y + (size_t)(mbase + 8) * Dc + nbase) = hi;
        }
    }
}

// ---------------- 5) LayerNorm over D=512 -----------------------------------
__global__ void k_ln(const float* __restrict__ Y, const float* __restrict__ gam,
                     const float* __restrict__ bet, float* __restrict__ out) {
    int row = blockIdx.x;
    const float* y = Y + (size_t)row * Dc;
    int t = threadIdx.x;
    float v[4];
    float s = 0.f;
#pragma unroll
    for (int i = 0; i < 4; i++) { v[i] = y[t + i * 128]; s += v[i]; }
    __shared__ float red[4];
#pragma unroll
    for (int o = 16; o; o >>= 1) s += __shfl_xor_sync(0xffffffffu, s, o);
    if ((t & 31) == 0) red[t >> 5] = s;
    __syncthreads();
    float mu = (red[0] + red[1] + red[2] + red[3]) * (1.f / Dc);
    __syncthreads();
    float d2 = 0.f;
#pragma unroll
    for (int i = 0; i < 4; i++) { float d = v[i] - mu; d2 += d * d; }
#pragma unroll
    for (int o = 16; o; o >>= 1) d2 += __shfl_xor_sync(0xffffffffu, d2, o);
    if ((t & 31) == 0) red[t >> 5] = d2;
    __syncthreads();
    float var = (red[0] + red[1] + red[2] + red[3]) * (1.f / Dc);
    float rs = rsqrtf(var + 1e-5f);
#pragma unroll
    for (int i = 0; i < 4; i++) {
        int c = t + i * 128;
        out[(size_t)row * Dc + c] = (v[i] - mu) * rs * gam[c] + bet[c];
    }
}

// ---------------- launch -----------------------------------------------------
extern "C" void kernel_launch(void* const* d_in, const int* in_sizes, int n_in,
                              void* d_out, int out_size) {
    const float* x      = (const float*)d_in[0];
    const int*   he     = (const int*)  d_in[1];
    const float* lin_w  = (const float*)d_in[2];
    const float* lin_b  = (const float*)d_in[3];
    const float* comb_w = (const float*)d_in[4];
    const float* comb_b = (const float*)d_in[5];
    const float* ln_g   = (const float*)d_in[6];
    const float* ln_b   = (const float*)d_in[7];
    float* out = (float*)d_out;
    const int nnz = in_sizes[1] / 2;

    float *p_y, *p_partW, *p_partb, *p_partW2, *p_partb2;
    cudaGetSymbolAddress((void**)&p_y,      g_y);
    cudaGetSymbolAddress((void**)&p_partW,  g_partW);
    cudaGetSymbolAddress((void**)&p_partb,  g_partb);
    cudaGetSymbolAddress((void**)&p_partW2, g_partW2);
    cudaGetSymbolAddress((void**)&p_partb2, g_partb2);

    cudaFuncSetAttribute(k_main_mma,
                         cudaFuncAttributeMaxDynamicSharedMemorySize, MM_SMEM);

    // 1) fused: fold1 (blocks 0-255) + weighted expert reduce (blocks 256-2303)
    {
        int grid = FOLD_BLOCKS + Gc * (Dc / 4) / 256;   // 256 + 2048
        k_red_fold<<<grid, 256>>>(x, he, nnz, lin_w, lin_w + Dc * Dc, lin_b,
                                  p_partW, p_partb);
    }

    // 2) fold2': (sum partW) @ comb_w ; bias GEMV on inline-computed b1f
    {
        dim3 grid(Dc / 64, Dc / 64, KZ);
        k_fold2<<<grid, 256>>>(he, nnz, comb_w, lin_b, p_partW, p_partb,
                               p_partW2, p_partb2);
    }

    // 3) combine -> Wf^T split-bf16 + bf
    k_comb2<<<Dc * Dc / 4 / 256, 256>>>(comb_b);

    // 4) main GEMM on tensor cores (mma.sync + ldmatrix): y = gelu(z0@Wf + bf)
    {
        dim3 grid(Dc / 128, Gc / 128);   // (4, 32) = 128 CTAs = 1 wave
        k_main_mma<<<grid, 512, MM_SMEM>>>();
    }

    // 5) LayerNorm -> output
    k_ln<<<Gc, 128>>>(p_y, ln_g, ln_b, out);
}

// round 15
// speedup vs baseline: 1.0821x; 1.0422x over previous
#include <cuda_runtime.h>
#include <cuda_bf16.h>
#include <math.h>
#include <stdint.h>

// Problem constants: B=4, L=1024, E=8, D=512, NLAYERS=2
#define Dc 512
#define Gc 4096   // B*L
#define Ec 8
#define MAXEDGE 256
#define KZ 4      // split-K factor for fold GEMMs
#define KLEN 128  // Dc / KZ
#define FOLD_BLOCKS 256

// ---------------- scratch (device globals; no allocations allowed) ----------
__device__ __align__(16) float g_partW[KZ * Dc * Dc];   // fold1 partials
__device__ __align__(16) float g_partb[KZ * Dc];
__device__ __align__(16) float g_partW2[KZ * Dc * Dc];  // fold2 partials
__device__ __align__(16) float g_partb2[KZ * Dc];
__device__ __align__(16) float g_bf[Dc];
__device__ __align__(16) __nv_bfloat16 g_z0h[Gc*Dc];   // hi(z0)       [m][k]
__device__ __align__(16) __nv_bfloat16 g_z0l[Gc*Dc];   // lo residual  [m][k]
__device__ __align__(16) __nv_bfloat16 g_Wfh[Dc*Dc];   // hi(Wf^T)     [n][k]
__device__ __align__(16) __nv_bfloat16 g_Wfl[Dc*Dc];   // lo(Wf^T)     [n][k]
__device__ __align__(16) float g_y[Gc*Dc];

// ---------------- f32x2 packed helpers (FFMA2, for fold GEMMs) --------------
__device__ __forceinline__ unsigned long long bcast2(float x) {
    unsigned long long r;
    asm("mov.b64 %0, {%1, %1};" : "=l"(r) : "f"(x));
    return r;
}
__device__ __forceinline__ void fma2(unsigned long long& d,
                                     unsigned long long a, unsigned long long b) {
    asm("fma.rn.f32x2 %0, %1, %2, %0;" : "+l"(d) : "l"(a), "l"(b));
}
__device__ __forceinline__ float2 unpack2(unsigned long long p) {
    float2 v;
    asm("mov.b64 {%0, %1}, %2;" : "=f"(v.x), "=f"(v.y) : "l"(p));
    return v;
}
__device__ __forceinline__ unsigned short bfu(__nv_bfloat16 h) {
    return *reinterpret_cast<unsigned short*>(&h);
}

// ---------------- 1) fused reduce + fold1 -----------------------------------
__global__ void __launch_bounds__(256)
k_red_fold(const float* __restrict__ X, const int* __restrict__ he, int nnz,
           const float* __restrict__ A, const float* __restrict__ B,
           const float* __restrict__ vsrc,
           float* __restrict__ partW, float* __restrict__ partb) {
    __shared__ float M2s[Ec][Ec];
    __shared__ float degn[Ec];
    __shared__ float dege[MAXEDGE];
    __shared__ float Dinv[Ec];
    __shared__ float Binv[MAXEDGE];
    __shared__ float w1s[Ec];
    __shared__ __align__(16) float As[2][16][68];
    __shared__ __align__(16) float Bs[2][16][68];
    __shared__ float vsm[KLEN];

    const int t = threadIdx.x;

    if (blockIdx.x < FOLD_BLOCKS) {
        constexpr int BM = 64, BN = 64, BK = 16, TM = 4, TN = 4;
        const int fid = blockIdx.x;
        const int bx = fid & 7, by = (fid >> 3) & 7, kz = fid >> 6;
        const int brow = by * BM;
        const int bcol = bx * BN;
        const int kbase = kz * KLEN;
        const int tcol = (t % (BN / TN)) * TN;
        const int trow = (t / (BN / TN)) * TM;
        const int ar = t / (BK / 4);
        const int ac = (t % (BK / 4)) * 4;
        const int br = t / (BN / 4);
        const int bc = (t % (BN / 4)) * 4;

        for (int i = t; i < KLEN; i += 256) vsm[i] = vsrc[kbase + i];
        const bool bth = (by == 0) && (t < BN);
        float bacc = 0.f;

        unsigned long long accp[TM / 2][TN];
#pragma unroll
        for (int m = 0; m < TM / 2; m++)
#pragma unroll
            for (int n = 0; n < TN; n++) accp[m][n] = 0ull;

        float4 afrag, bfrag;
        auto ldg = [&](int k0) {
            afrag = *reinterpret_cast<const float4*>(
                &A[(size_t)(brow + ar) * Dc + kbase + k0 + ac]);
            bfrag = *reinterpret_cast<const float4*>(
                &B[(size_t)(kbase + k0 + br) * Dc + bcol + bc]);
        };
        auto sts = [&](int buf) {
            As[buf][ac + 0][ar] = afrag.x;
            As[buf][ac + 1][ar] = afrag.y;
            As[buf][ac + 2][ar] = afrag.z;
            As[buf][ac + 3][ar] = afrag.w;
            *reinterpret_cast<float4*>(&Bs[buf][br][bc]) = bfrag;
        };

        ldg(0);
        sts(0);
        __syncthreads();

        int buf = 0;
        for (int k0 = 0; k0 < KLEN; k0 += BK) {
            const bool has_next = (k0 + BK) < KLEN;
            if (has_next) ldg(k0 + BK);
#pragma unroll
            for (int kk = 0; kk < BK; kk++) {
                unsigned long long rap[TM / 2];
                const unsigned long long* ap =
                    reinterpret_cast<const unsigned long long*>(&As[buf][kk][trow]);
#pragma unroll
                for (int m = 0; m < TM / 2; m++) rap[m] = ap[m];
                float rb[TN];
#pragma unroll
                for (int n = 0; n < TN; n += 4)
                    *reinterpret_cast<float4*>(&rb[n]) =
                        *reinterpret_cast<const float4*>(&Bs[buf][kk][tcol + n]);
                unsigned long long rbb[TN];
#pragma unroll
                for (int n = 0; n < TN; n++) rbb[n] = bcast2(rb[n]);
#pragma unroll
                for (int m = 0; m < TM / 2; m++)
#pragma unroll
                    for (int n = 0; n < TN; n++) fma2(accp[m][n], rap[m], rbb[n]);
            }
            if (bth) {
#pragma unroll 4
                for (int kk = 0; kk < BK; kk++)
                    bacc = fmaf(vsm[k0 + kk], Bs[buf][kk][t], bacc);
            }
            if (has_next) {
                sts(buf ^ 1);
                __syncthreads();
                buf ^= 1;
            }
        }

        if (bth) partb[kz * Dc + bcol + t] = bacc;
        float* W = partW + (size_t)kz * Dc * Dc;
#pragma unroll
        for (int m = 0; m < TM / 2; m++)
#pragma unroll
            for (int n = 0; n < TN; n++) {
                float2 v = unpack2(accp[m][n]);
                W[(size_t)(brow + trow + 2 * m + 0) * Dc + bcol + tcol + n] = v.x;
                W[(size_t)(brow + trow + 2 * m + 1) * Dc + bcol + tcol + n] = v.y;
            }
    } else {
        const int* node = he;
        const int* edge = he + nnz;
        if (t < Ec) degn[t] = 0.f;
        for (int e = t; e < MAXEDGE; e += 256) dege[e] = 0.f;
        if (t < Ec * Ec) ((float*)M2s)[t] = 0.f;
        __syncthreads();
        for (int i = t; i < nnz; i += 256) {
            atomicAdd(&degn[node[i]], 1.f);
            atomicAdd(&dege[edge[i]], 1.f);
        }
        __syncthreads();
        if (t < Ec) Dinv[t] = degn[t] > 0.f ? 1.f / degn[t] : 0.f;
        for (int e = t; e < MAXEDGE; e += 256)
            Binv[e] = dege[e] > 0.f ? 1.f / dege[e] : 0.f;
        __syncthreads();
        int total = nnz * nnz;
        for (int p = t; p < total; p += 256) {
            int i = p % nnz, j = p / nnz;
            int ei = edge[i];
            if (ei == edge[j])
                atomicAdd(&M2s[node[j]][node[i]], Dinv[node[j]] * Binv[ei]);
        }
        __syncthreads();
        if (t == 0) {
            float w2[Ec];
            for (int u = 0; u < Ec; u++) {
                float s = 0.f;
                for (int v = 0; v < Ec; v++) s += M2s[v][u];
                w2[u] = s / (float)Ec;
            }
            for (int q = 0; q < Ec; q++) {
                float s = 0.f;
                for (int u = 0; u < Ec; u++) s += M2s[u][q] * w2[u];
                w1s[q] = s;
            }
        }
        __syncthreads();

        int i = (blockIdx.x - FOLD_BLOCKS) * 256 + t;
        int g  = i >> 7;
        int d4 = i & 127;
        const float4* xp =
            reinterpret_cast<const float4*>(X) + (size_t)g * Ec * (Dc / 4) + d4;
        float w[Ec];
#pragma unroll
        for (int u = 0; u < Ec; u++) w[u] = w1s[u];
        float4 acc = make_float4(0.f, 0.f, 0.f, 0.f);
#pragma unroll
        for (int u = 0; u < Ec; u++) {
            float4 v = xp[(size_t)u * (Dc / 4)];
            acc.x = fmaf(w[u], v.x, acc.x);
            acc.y = fmaf(w[u], v.y, acc.y);
            acc.z = fmaf(w[u], v.z, acc.z);
            acc.w = fmaf(w[u], v.w, acc.w);
        }
        float a[4] = {acc.x, acc.y, acc.z, acc.w};
        unsigned short h[4], l[4];
#pragma unroll
        for (int j = 0; j < 4; j++) {
            __nv_bfloat16 hb = __float2bfloat16(a[j]);
            __nv_bfloat16 lb = __float2bfloat16(a[j] - __bfloat162float(hb));
            h[j] = bfu(hb);
            l[j] = bfu(lb);
        }
        uint2 uh, ul;
        uh.x = (uint32_t)h[0] | ((uint32_t)h[1] << 16);
        uh.y = (uint32_t)h[2] | ((uint32_t)h[3] << 16);
        ul.x = (uint32_t)l[0] | ((uint32_t)l[1] << 16);
        ul.y = (uint32_t)l[2] | ((uint32_t)l[3] << 16);
        *reinterpret_cast<uint2*>(g_z0h + (size_t)i * 4) = uh;
        *reinterpret_cast<uint2*>(g_z0l + (size_t)i * 4) = ul;
    }
}

// ---------------- 2) fold2': (sum of fold1 partials) @ comb_w ---------------
__global__ void __launch_bounds__(256)
k_fold2(const int* __restrict__ he, int nnz,
        const float* __restrict__ Bmat, const float* __restrict__ lin_b,
        const float* __restrict__ pW1, const float* __restrict__ pb1,
        float* __restrict__ partW, float* __restrict__ partb) {
    constexpr int BM = 64, BN = 64, BK = 16, TM = 4, TN = 4;
    __shared__ __align__(16) float As[2][BK][BM + 4];
    __shared__ __align__(16) float Bs[2][BK][BN + 4];
    __shared__ float vsm[KLEN];
    __shared__ float M2s[Ec][Ec];
    __shared__ float degn[Ec];
    __shared__ float dege[MAXEDGE];
    __shared__ float Dinv[Ec];
    __shared__ float Binv[MAXEDGE];
    __shared__ float s2s;

    const int t = threadIdx.x;
    const int brow = blockIdx.y * BM;
    const int bcol = blockIdx.x * BN;
    const int kz   = blockIdx.z;
    const int kbase = kz * KLEN;
    const int tcol = (t % (BN / TN)) * TN;
    const int trow = (t / (BN / TN)) * TM;
    const int ar = t / (BK / 4);
    const int ac = (t % (BK / 4)) * 4;
    const int br = t / (BN / 4);
    const int bc = (t % (BN / 4)) * 4;

    if (blockIdx.y == 0) {
        const int* node = he;
        const int* edge = he + nnz;
        if (t < Ec) degn[t] = 0.f;
        for (int e = t; e < MAXEDGE; e += 256) dege[e] = 0.f;
        if (t < Ec * Ec) ((float*)M2s)[t] = 0.f;
        __syncthreads();
        for (int i = t; i < nnz; i += 256) {
            atomicAdd(&degn[node[i]], 1.f);
            atomicAdd(&dege[edge[i]], 1.f);
        }
        __syncthreads();
        if (t < Ec) Dinv[t] = degn[t] > 0.f ? 1.f / degn[t] : 0.f;
        for (int e = t; e < MAXEDGE; e += 256)
            Binv[e] = dege[e] > 0.f ? 1.f / dege[e] : 0.f;
        __syncthreads();
        int total = nnz * nnz;
        for (int p = t; p < total; p += 256) {
            int i = p % nnz, j = p / nnz;
            int ei = edge[i];
            if (ei == edge[j])
                atomicAdd(&M2s[node[j]][node[i]], Dinv[node[j]] * Binv[ei]);
        }
        __syncthreads();
        if (t == 0) {
            float s2 = 0.f;
            for (int u = 0; u < Ec; u++) {
                float s = 0.f;
                for (int v = 0; v < Ec; v++) s += M2s[v][u];
                s2 += s / (float)Ec;
            }
            s2s = s2;
        }
        __syncthreads();
        for (int i = t; i < KLEN; i += 256) {
            float s = ((pb1[kbase + i] + pb1[Dc + kbase + i])
                       + pb1[2 * Dc + kbase + i]) + pb1[3 * Dc + kbase + i];
            vsm[i] = s2s * s + lin_b[Dc + kbase + i];
        }
    }
    const bool bth = (blockIdx.y == 0) && (t < BN);
    float bacc = 0.f;

    unsigned long long accp[TM / 2][TN];
#pragma unroll
    for (int m = 0; m < TM / 2; m++)
#pragma unroll
        for (int n = 0; n < TN; n++) accp[m][n] = 0ull;

    float4 afrag, bfrag;
    auto ldg = [&](int k0) {
        size_t aidx = (size_t)(brow + ar) * Dc + kbase + k0 + ac;
        float4 p0 = *reinterpret_cast<const float4*>(pW1 + aidx);
        float4 p1 = *reinterpret_cast<const float4*>(pW1 + (size_t)Dc * Dc + aidx);
        float4 p2 = *reinterpret_cast<const float4*>(pW1 + 2 * (size_t)Dc * Dc + aidx);
        float4 p3 = *reinterpret_cast<const float4*>(pW1 + 3 * (size_t)Dc * Dc + aidx);
        afrag.x = ((p0.x + p1.x) + p2.x) + p3.x;
        afrag.y = ((p0.y + p1.y) + p2.y) + p3.y;
        afrag.z = ((p0.z + p1.z) + p2.z) + p3.z;
        afrag.w = ((p0.w + p1.w) + p2.w) + p3.w;
        bfrag = *reinterpret_cast<const float4*>(
            &Bmat[(size_t)(kbase + k0 + br) * Dc + bcol + bc]);
    };
    auto sts = [&](int buf) {
        As[buf][ac + 0][ar] = afrag.x;
        As[buf][ac + 1][ar] = afrag.y;
        As[buf][ac + 2][ar] = afrag.z;
        As[buf][ac + 3][ar] = afrag.w;
        *reinterpret_cast<float4*>(&Bs[buf][br][bc]) = bfrag;
    };

    ldg(0);
    sts(0);
    __syncthreads();

    int buf = 0;
    for (int k0 = 0; k0 < KLEN; k0 += BK) {
        const bool has_next = (k0 + BK) < KLEN;
        if (has_next) ldg(k0 + BK);
#pragma unroll
        for (int kk = 0; kk < BK; kk++) {
            unsigned long long rap[TM / 2];
            const unsigned long long* ap =
                reinterpret_cast<const unsigned long long*>(&As[buf][kk][trow]);
#pragma unroll
            for (int m = 0; m < TM / 2; m++) rap[m] = ap[m];
            float rb[TN];
#pragma unroll
            for (int n = 0; n < TN; n += 4)
                *reinterpret_cast<float4*>(&rb[n]) =
                    *reinterpret_cast<const float4*>(&Bs[buf][kk][tcol + n]);
            unsigned long long rbb[TN];
#pragma unroll
            for (int n = 0; n < TN; n++) rbb[n] = bcast2(rb[n]);
#pragma unroll
            for (int m = 0; m < TM / 2; m++)
#pragma unroll
                for (int n = 0; n < TN; n++) fma2(accp[m][n], rap[m], rbb[n]);
        }
        if (bth) {
#pragma unroll 4
            for (int kk = 0; kk < BK; kk++)
                bacc = fmaf(vsm[k0 + kk], Bs[buf][kk][t], bacc);
        }
        if (has_next) {
            sts(buf ^ 1);
            __syncthreads();
            buf ^= 1;
        }
    }

    if (bth) partb[kz * Dc + bcol + t] = bacc;
    float* W = partW + (size_t)kz * Dc * Dc;
#pragma unroll
    for (int m = 0; m < TM / 2; m++)
#pragma unroll
        for (int n = 0; n < TN; n++) {
            float2 v = unpack2(accp[m][n]);
            W[(size_t)(brow + trow + 2 * m + 0) * Dc + bcol + tcol + n] = v.x;
            W[(size_t)(brow + trow + 2 * m + 1) * Dc + bcol + tcol + n] = v.y;
        }
}

// ---------------- 3) combine -> Wf^T split-bf16 + bf ------------------------
__global__ void k_comb2(const float* __restrict__ extra_b) {
    int i = blockIdx.x * blockDim.x + threadIdx.x;
    const float4* p = reinterpret_cast<const float4*>(g_partW2);
    constexpr int STRIDE = Dc * Dc / 4;
    float4 a = p[i], b = p[i + STRIDE], c = p[i + 2 * STRIDE], d = p[i + 3 * STRIDE];
    float r[4];
    r[0] = ((a.x + b.x) + c.x) + d.x;
    r[1] = ((a.y + b.y) + c.y) + d.y;
    r[2] = ((a.z + b.z) + c.z) + d.z;
    r[3] = ((a.w + b.w) + c.w) + d.w;
    int k = i >> 7;
    int n = (i & 127) * 4;
#pragma unroll
    for (int j = 0; j < 4; j++) {
        __nv_bfloat16 hb = __float2bfloat16(r[j]);
        __nv_bfloat16 lb = __float2bfloat16(r[j] - __bfloat162float(hb));
        g_Wfh[(size_t)(n + j) * Dc + k] = hb;
        g_Wfl[(size_t)(n + j) * Dc + k] = lb;
    }
    if (i < Dc) {
        float s = ((g_partb2[i] + g_partb2[Dc + i]) + g_partb2[2 * Dc + i])
                  + g_partb2[3 * Dc + i];
        g_bf[i] = s + extra_b[i];
    }
}

// ---------------- 4) main GEMM: mma.sync bf16-split, pipelined --------------
// 256 threads, 8 warps as 2(m) x 4(n), warp tile 64x32, BK=16.
// 3-stage pipeline: smem(kt+1) ready before mma(kt); fragments double-buffered
// in registers so LDSM of kt+1 overlaps HMMA of kt.
#define MM_BK   16
#define MM_LDK  24                      // padded row -> 48B, ldmatrix conflict-free
#define MM_TILE (128 * MM_LDK)
#define MM_BUF  (4 * MM_TILE)           // Ah, Al, Bh, Bl
#define MM_SMEM (2 * MM_BUF * 2)        // 49152 bytes

__device__ __forceinline__ void mma16816(float* c, uint32_t a0, uint32_t a1,
                                         uint32_t a2, uint32_t a3,
                                         uint32_t b0, uint32_t b1) {
    asm volatile(
        "mma.sync.aligned.m16n8k16.row.col.f32.bf16.bf16.f32 "
        "{%0,%1,%2,%3}, {%4,%5,%6,%7}, {%8,%9}, {%0,%1,%2,%3};"
        : "+f"(c[0]), "+f"(c[1]), "+f"(c[2]), "+f"(c[3])
        : "r"(a0), "r"(a1), "r"(a2), "r"(a3), "r"(b0), "r"(b1));
}

__device__ __forceinline__ void ldm_x4(uint32_t& r0, uint32_t& r1,
                                       uint32_t& r2, uint32_t& r3, uint32_t addr) {
    asm volatile(
        "ldmatrix.sync.aligned.m8n8.x4.shared.b16 {%0,%1,%2,%3}, [%4];"
        : "=r"(r0), "=r"(r1), "=r"(r2), "=r"(r3) : "r"(addr));
}

__global__ void __launch_bounds__(256, 1) k_main_mma() {
    extern __shared__ __nv_bfloat16 sm[];
    const int tid  = threadIdx.x;
    const int lane = tid & 31;
    const int wid  = tid >> 5;          // 0..7
    const int wm   = wid >> 2;          // 0..1 -> m offset wm*64
    const int wn   = wid & 3;           // 0..3 -> n offset wn*32
    const int brow = blockIdx.y * 128;
    const int bcol = blockIdx.x * 128;
    const int g    = lane >> 2;
    const int tg   = lane & 3;

    // staging: 256 threads, 1 uint4 (16B) per tile per thread
    const int r0 = tid >> 1, c0 = (tid & 1) * 8;

    // ldmatrix lane address components
    const int sel = lane >> 3;
    const int rim = lane & 7;
    const int a_row = (sel & 1) * 8 + rim;
    const int a_k   = (sel >> 1) * 8;
    const int b_row = (sel >> 1) * 8 + rim;
    const int b_k   = (sel & 1) * 8;

    float acc[4][4][4];
#pragma unroll
    for (int mf = 0; mf < 4; mf++)
#pragma unroll
        for (int nf = 0; nf < 4; nf++)
#pragma unroll
            for (int q = 0; q < 4; q++) acc[mf][nf][q] = 0.f;

    uint4 pf[4];
    auto ldg = [&](int kb) {
        pf[0] = *(const uint4*)(g_z0h + (size_t)(brow + r0) * Dc + kb + c0);
        pf[1] = *(const uint4*)(g_z0l + (size_t)(brow + r0) * Dc + kb + c0);
        pf[2] = *(const uint4*)(g_Wfh + (size_t)(bcol + r0) * Dc + kb + c0);
        pf[3] = *(const uint4*)(g_Wfl + (size_t)(bcol + r0) * Dc + kb + c0);
    };
    auto sts = [&](int buf) {
        __nv_bfloat16* base = sm + buf * MM_BUF + r0 * MM_LDK + c0;
#pragma unroll
        for (int a = 0; a < 4; a++)
            *(uint4*)(base + a * MM_TILE) = pf[a];
    };

    uint32_t Ah0[4][4], Al0[4][4], Bh0[4][2], Bl0[4][2];
    uint32_t Ah1[4][4], Al1[4][4], Bh1[4][2], Bl1[4][2];

#define LOADF(AH, AL, BH, BL, bidx) do {                                       \
    const __nv_bfloat16* base_ = sm + (bidx) * MM_BUF;                         \
    _Pragma("unroll")                                                          \
    for (int mf = 0; mf < 4; mf++) {                                           \
        uint32_t a1_ = (uint32_t)__cvta_generic_to_shared(                     \
            base_ + 0 * MM_TILE + (wm * 64 + mf * 16 + a_row) * MM_LDK + a_k); \
        ldm_x4(AH[mf][0], AH[mf][1], AH[mf][2], AH[mf][3], a1_);               \
        uint32_t a2_ = (uint32_t)__cvta_generic_to_shared(                     \
            base_ + 1 * MM_TILE + (wm * 64 + mf * 16 + a_row) * MM_LDK + a_k); \
        ldm_x4(AL[mf][0], AL[mf][1], AL[mf][2], AL[mf][3], a2_);               \
    }                                                                          \
    _Pragma("unroll")                                                          \
    for (int nf2 = 0; nf2 < 2; nf2++) {                                        \
        uint32_t b1_ = (uint32_t)__cvta_generic_to_shared(                     \
            base_ + 2 * MM_TILE + (wn * 32 + nf2 * 16 + b_row) * MM_LDK + b_k);\
        ldm_x4(BH[nf2 * 2][0], BH[nf2 * 2][1],                                 \
               BH[nf2 * 2 + 1][0], BH[nf2 * 2 + 1][1], b1_);                   \
        uint32_t b2_ = (uint32_t)__cvta_generic_to_shared(                     \
            base_ + 3 * MM_TILE + (wn * 32 + nf2 * 16 + b_row) * MM_LDK + b_k);\
        ldm_x4(BL[nf2 * 2][0], BL[nf2 * 2][1],                                 \
               BL[nf2 * 2 + 1][0], BL[nf2 * 2 + 1][1], b2_);                   \
    }                                                                          \
} while (0)

#define MMAS(AH, AL, BH, BL) do {                                              \
    _Pragma("unroll")                                                          \
    for (int mf = 0; mf < 4; mf++)                                             \
    _Pragma("unroll")                                                          \
    for (int nf = 0; nf < 4; nf++) {                                           \
        mma16816(acc[mf][nf], AH[mf][0], AH[mf][1], AH[mf][2], AH[mf][3],      \
                 BH[nf][0], BH[nf][1]);                                        \
        mma16816(acc[mf][nf], AH[mf][0], AH[mf][1], AH[mf][2], AH[mf][3],      \
                 BL[nf][0], BL[nf][1]);                                        \
        mma16816(acc[mf][nf], AL[mf][0], AL[mf][1], AL[mf][2], AL[mf][3],      \
                 BH[nf][0], BH[nf][1]);                                        \
    }                                                                          \
} while (0)

    // prologue: tile 0 in smem buf0 + fragments; tile 1 staged in regs
    ldg(0);
    sts(0);
    __syncthreads();
    LOADF(Ah0, Al0, Bh0, Bl0, 0);
    ldg(MM_BK);

    for (int kt = 0; kt < 32; kt += 2) {
        // stage A: smem+frags for kt+1 (buf1, set1); compute kt (set0)
        sts(1);
        __syncthreads();
        LOADF(Ah1, Al1, Bh1, Bl1, 1);
        if (kt + 2 < 32) ldg((kt + 2) * MM_BK);
        MMAS(Ah0, Al0, Bh0, Bl0);
        // stage B: smem+frags for kt+2 (buf0, set0); compute kt+1 (set1)
        if (kt + 2 < 32) {
            sts(0);
            __syncthreads();
            LOADF(Ah0, Al0, Bh0, Bl0, 0);
            if (kt + 3 < 32) ldg((kt + 3) * MM_BK);
        }
        MMAS(Ah1, Al1, Bh1, Bl1);
    }

    // epilogue: bias + exact GELU
#pragma unroll
    for (int mf = 0; mf < 4; mf++) {
#pragma unroll
        for (int nf = 0; nf < 4; nf++) {
            int mbase = brow + wm * 64 + mf * 16 + g;
            int nbase = bcol + wn * 32 + nf * 8 + tg * 2;
            float b0v = g_bf[nbase], b1v = g_bf[nbase + 1];
            float x0 = acc[mf][nf][0] + b0v;
            float x1 = acc[mf][nf][1] + b1v;
            float x2 = acc[mf][nf][2] + b0v;
            float x3 = acc[mf][nf][3] + b1v;
            float2 lo, hi;
            lo.x = 0.5f * x0 * (1.f + erff(x0 * 0.70710678118654752f));
            lo.y = 0.5f * x1 * (1.f + erff(x1 * 0.70710678118654752f));
            hi.x = 0.5f * x2 * (1.f + erff(x2 * 0.70710678118654752f));
            hi.y = 0.5f * x3 * (1.f + erff(x3 * 0.70710678118654752f));
            *reinterpret_cast<float2*>(g_y + (size_t)mbase * Dc + nbase) = lo;
            *reinterpret_cast<float2*>(g_y + (size_t)(mbase + 8) * Dc + nbase) = hi;
        }
    }
}

// ---------------- 5) LayerNorm over D=512 -----------------------------------
__global__ void k_ln(const float* __restrict__ Y, const float* __restrict__ gam,
                     const float* __restrict__ bet, float* __restrict__ out) {
    int row = blockIdx.x;
    const float* y = Y + (size_t)row * Dc;
    int t = threadIdx.x;
    float v[4];
    float s = 0.f;
#pragma unroll
    for (int i = 0; i < 4; i++) { v[i] = y[t + i * 128]; s += v[i]; }
    __shared__ float red[4];
#pragma unroll
    for (int o = 16; o; o >>= 1) s += __shfl_xor_sync(0xffffffffu, s, o);
    if ((t & 31) == 0) red[t >> 5] = s;
    __syncthreads();
    float mu = (red[0] + red[1] + red[2] + red[3]) * (1.f / Dc);
    __syncthreads();
    float d2 = 0.f;
#pragma unroll
    for (int i = 0; i < 4; i++) { float d = v[i] - mu; d2 += d * d; }
#pragma unroll
    for (int o = 16; o; o >>= 1) d2 += __shfl_xor_sync(0xffffffffu, d2, o);
    if ((t & 31) == 0) red[t >> 5] = d2;
    __syncthreads();
    float var = (red[0] + red[1] + red[2] + red[3]) * (1.f / Dc);
    float rs = rsqrtf(var + 1e-5f);
#pragma unroll
    for (int i = 0; i < 4; i++) {
        int c = t + i * 128;
        out[(size_t)row * Dc + c] = (v[i] - mu) * rs * gam[c] + bet[c];
    }
}

// ---------------- launch -----------------------------------------------------
extern "C" void kernel_launch(void* const* d_in, const int* in_sizes, int n_in,
                              void* d_out, int out_size) {
    const float* x      = (const float*)d_in[0];
    const int*   he     = (const int*)  d_in[1];
    const float* lin_w  = (const float*)d_in[2];
    const float* lin_b  = (const float*)d_in[3];
    const float* comb_w = (const float*)d_in[4];
    const float* comb_b = (const float*)d_in[5];
    const float* ln_g   = (const float*)d_in[6];
    const float* ln_b   = (const float*)d_in[7];
    float* out = (float*)d_out;
    const int nnz = in_sizes[1] / 2;

    float *p_y, *p_partW, *p_partb, *p_partW2, *p_partb2;
    cudaGetSymbolAddress((void**)&p_y,      g_y);
    cudaGetSymbolAddress((void**)&p_partW,  g_partW);
    cudaGetSymbolAddress((void**)&p_partb,  g_partb);
    cudaGetSymbolAddress((void**)&p_partW2, g_partW2);
    cudaGetSymbolAddress((void**)&p_partb2, g_partb2);

    cudaFuncSetAttribute(k_main_mma,
                         cudaFuncAttributeMaxDynamicSharedMemorySize, MM_SMEM);

    // 1) fused: fold1 (blocks 0-255) + weighted expert reduce (blocks 256-2303)
    {
        int grid = FOLD_BLOCKS + Gc * (Dc / 4) / 256;   // 256 + 2048
        k_red_fold<<<grid, 256>>>(x, he, nnz, lin_w, lin_w + Dc * Dc, lin_b,
                                  p_partW, p_partb);
    }

    // 2) fold2': (sum partW) @ comb_w ; bias GEMV on inline-computed b1f
    {
        dim3 grid(Dc / 64, Dc / 64, KZ);
        k_fold2<<<grid, 256>>>(he, nnz, comb_w, lin_b, p_partW, p_partb,
                               p_partW2, p_partb2);
    }

    // 3) combine -> Wf^T split-bf16 + bf
    k_comb2<<<Dc * Dc / 4 / 256, 256>>>(comb_b);

    // 4) main GEMM (mma.sync, ldmatrix, reg-pipelined): y = gelu(z0@Wf + bf)
    {
        dim3 grid(Dc / 128, Gc / 128);   // (4, 32) = 128 CTAs = 1 wave
        k_main_mma<<<grid, 256, MM_SMEM>>>();
    }

    // 5) LayerNorm -> output
    k_ln<<<Gc, 128>>>(p_y, ln_g, ln_b, out);
}

// round 16
// speedup vs baseline: 1.1049x; 1.0210x over previous
#include <cuda_runtime.h>
#include <cuda_bf16.h>
#include <math.h>
#include <stdint.h>

// Problem constants: B=4, L=1024, E=8, D=512, NLAYERS=2
#define Dc 512
#define Gc 4096   // B*L
#define Ec 8
#define MAXEDGE 256
#define KZ 4      // split-K factor for fold GEMMs
#define KLEN 128  // Dc / KZ
#define FOLD_BLOCKS 256

// ---------------- scratch (device globals; no allocations allowed) ----------
__device__ __align__(16) float g_partW[KZ * Dc * Dc];   // fold1 partials
__device__ __align__(16) float g_partb[KZ * Dc];
__device__ __align__(16) float g_partW2[KZ * Dc * Dc];  // fold2 partials
__device__ __align__(16) float g_partb2[KZ * Dc];
__device__ __align__(16) float g_bf[Dc];
__device__ __align__(16) __nv_bfloat16 g_z0h[Gc*Dc];   // hi(z0)       [m][k]
__device__ __align__(16) __nv_bfloat16 g_z0l[Gc*Dc];   // lo residual  [m][k]
__device__ __align__(16) __nv_bfloat16 g_Wfh[Dc*Dc];   // hi(Wf^T)     [n][k]
__device__ __align__(16) __nv_bfloat16 g_Wfl[Dc*Dc];   // lo(Wf^T)     [n][k]
__device__ __align__(16) float g_y[Gc*Dc];

// ---------------- f32x2 packed helpers (FFMA2, for fold GEMMs) --------------
__device__ __forceinline__ unsigned long long bcast2(float x) {
    unsigned long long r;
    asm("mov.b64 %0, {%1, %1};" : "=l"(r) : "f"(x));
    return r;
}
__device__ __forceinline__ void fma2(unsigned long long& d,
                                     unsigned long long a, unsigned long long b) {
    asm("fma.rn.f32x2 %0, %1, %2, %0;" : "+l"(d) : "l"(a), "l"(b));
}
__device__ __forceinline__ float2 unpack2(unsigned long long p) {
    float2 v;
    asm("mov.b64 {%0, %1}, %2;" : "=f"(v.x), "=f"(v.y) : "l"(p));
    return v;
}
__device__ __forceinline__ unsigned short bfu(__nv_bfloat16 h) {
    return *reinterpret_cast<unsigned short*>(&h);
}

// ---------------- 1) fused reduce + fold1 -----------------------------------
__global__ void __launch_bounds__(256)
k_red_fold(const float* __restrict__ X, const int* __restrict__ he, int nnz,
           const float* __restrict__ A, const float* __restrict__ B,
           const float* __restrict__ vsrc,
           float* __restrict__ partW, float* __restrict__ partb) {
    __shared__ float M2s[Ec][Ec];
    __shared__ float degn[Ec];
    __shared__ float dege[MAXEDGE];
    __shared__ float Dinv[Ec];
    __shared__ float Binv[MAXEDGE];
    __shared__ float w1s[Ec];
    __shared__ __align__(16) float As[2][16][68];
    __shared__ __align__(16) float Bs[2][16][68];
    __shared__ float vsm[KLEN];

    const int t = threadIdx.x;

    if (blockIdx.x < FOLD_BLOCKS) {
        constexpr int BM = 64, BN = 64, BK = 16, TM = 4, TN = 4;
        const int fid = blockIdx.x;
        const int bx = fid & 7, by = (fid >> 3) & 7, kz = fid >> 6;
        const int brow = by * BM;
        const int bcol = bx * BN;
        const int kbase = kz * KLEN;
        const int tcol = (t % (BN / TN)) * TN;
        const int trow = (t / (BN / TN)) * TM;
        const int ar = t / (BK / 4);
        const int ac = (t % (BK / 4)) * 4;
        const int br = t / (BN / 4);
        const int bc = (t % (BN / 4)) * 4;

        for (int i = t; i < KLEN; i += 256) vsm[i] = vsrc[kbase + i];
        const bool bth = (by == 0) && (t < BN);
        float bacc = 0.f;

        unsigned long long accp[TM / 2][TN];
#pragma unroll
        for (int m = 0; m < TM / 2; m++)
#pragma unroll
            for (int n = 0; n < TN; n++) accp[m][n] = 0ull;

        float4 afrag, bfrag;
        auto ldg = [&](int k0) {
            afrag = *reinterpret_cast<const float4*>(
                &A[(size_t)(brow + ar) * Dc + kbase + k0 + ac]);
            bfrag = *reinterpret_cast<const float4*>(
                &B[(size_t)(kbase + k0 + br) * Dc + bcol + bc]);
        };
        auto sts = [&](int buf) {
            As[buf][ac + 0][ar] = afrag.x;
            As[buf][ac + 1][ar] = afrag.y;
            As[buf][ac + 2][ar] = afrag.z;
            As[buf][ac + 3][ar] = afrag.w;
            *reinterpret_cast<float4*>(&Bs[buf][br][bc]) = bfrag;
        };

        ldg(0);
        sts(0);
        __syncthreads();

        int buf = 0;
        for (int k0 = 0; k0 < KLEN; k0 += BK) {
            const bool has_next = (k0 + BK) < KLEN;
            if (has_next) ldg(k0 + BK);
#pragma unroll
            for (int kk = 0; kk < BK; kk++) {
                unsigned long long rap[TM / 2];
                const unsigned long long* ap =
                    reinterpret_cast<const unsigned long long*>(&As[buf][kk][trow]);
#pragma unroll
                for (int m = 0; m < TM / 2; m++) rap[m] = ap[m];
                float rb[TN];
#pragma unroll
                for (int n = 0; n < TN; n += 4)
                    *reinterpret_cast<float4*>(&rb[n]) =
                        *reinterpret_cast<const float4*>(&Bs[buf][kk][tcol + n]);
                unsigned long long rbb[TN];
#pragma unroll
                for (int n = 0; n < TN; n++) rbb[n] = bcast2(rb[n]);
#pragma unroll
                for (int m = 0; m < TM / 2; m++)
#pragma unroll
                    for (int n = 0; n < TN; n++) fma2(accp[m][n], rap[m], rbb[n]);
            }
            if (bth) {
#pragma unroll 4
                for (int kk = 0; kk < BK; kk++)
                    bacc = fmaf(vsm[k0 + kk], Bs[buf][kk][t], bacc);
            }
            if (has_next) {
                sts(buf ^ 1);
                __syncthreads();
                buf ^= 1;
            }
        }

        if (bth) partb[kz * Dc + bcol + t] = bacc;
        float* W = partW + (size_t)kz * Dc * Dc;
#pragma unroll
        for (int m = 0; m < TM / 2; m++)
#pragma unroll
            for (int n = 0; n < TN; n++) {
                float2 v = unpack2(accp[m][n]);
                W[(size_t)(brow + trow + 2 * m + 0) * Dc + bcol + tcol + n] = v.x;
                W[(size_t)(brow + trow + 2 * m + 1) * Dc + bcol + tcol + n] = v.y;
            }
    } else {
        const int* node = he;
        const int* edge = he + nnz;
        if (t < Ec) degn[t] = 0.f;
        for (int e = t; e < MAXEDGE; e += 256) dege[e] = 0.f;
        if (t < Ec * Ec) ((float*)M2s)[t] = 0.f;
        __syncthreads();
        for (int i = t; i < nnz; i += 256) {
            atomicAdd(&degn[node[i]], 1.f);
            atomicAdd(&dege[edge[i]], 1.f);
        }
        __syncthreads();
        if (t < Ec) Dinv[t] = degn[t] > 0.f ? 1.f / degn[t] : 0.f;
        for (int e = t; e < MAXEDGE; e += 256)
            Binv[e] = dege[e] > 0.f ? 1.f / dege[e] : 0.f;
        __syncthreads();
        int total = nnz * nnz;
        for (int p = t; p < total; p += 256) {
            int i = p % nnz, j = p / nnz;
            int ei = edge[i];
            if (ei == edge[j])
                atomicAdd(&M2s[node[j]][node[i]], Dinv[node[j]] * Binv[ei]);
        }
        __syncthreads();
        if (t == 0) {
            float w2[Ec];
            for (int u = 0; u < Ec; u++) {
                float s = 0.f;
                for (int v = 0; v < Ec; v++) s += M2s[v][u];
                w2[u] = s / (float)Ec;
            }
            for (int q = 0; q < Ec; q++) {
                float s = 0.f;
                for (int u = 0; u < Ec; u++) s += M2s[u][q] * w2[u];
                w1s[q] = s;
            }
        }
        __syncthreads();

        int i = (blockIdx.x - FOLD_BLOCKS) * 256 + t;
        int g  = i >> 7;
        int d4 = i & 127;
        const float4* xp =
            reinterpret_cast<const float4*>(X) + (size_t)g * Ec * (Dc / 4) + d4;
        float w[Ec];
#pragma unroll
        for (int u = 0; u < Ec; u++) w[u] = w1s[u];
        float4 acc = make_float4(0.f, 0.f, 0.f, 0.f);
#pragma unroll
        for (int u = 0; u < Ec; u++) {
            float4 v = xp[(size_t)u * (Dc / 4)];
            acc.x = fmaf(w[u], v.x, acc.x);
            acc.y = fmaf(w[u], v.y, acc.y);
            acc.z = fmaf(w[u], v.z, acc.z);
            acc.w = fmaf(w[u], v.w, acc.w);
        }
        float a[4] = {acc.x, acc.y, acc.z, acc.w};
        unsigned short h[4], l[4];
#pragma unroll
        for (int j = 0; j < 4; j++) {
            __nv_bfloat16 hb = __float2bfloat16(a[j]);
            __nv_bfloat16 lb = __float2bfloat16(a[j] - __bfloat162float(hb));
            h[j] = bfu(hb);
            l[j] = bfu(lb);
        }
        uint2 uh, ul;
        uh.x = (uint32_t)h[0] | ((uint32_t)h[1] << 16);
        uh.y = (uint32_t)h[2] | ((uint32_t)h[3] << 16);
        ul.x = (uint32_t)l[0] | ((uint32_t)l[1] << 16);
        ul.y = (uint32_t)l[2] | ((uint32_t)l[3] << 16);
        *reinterpret_cast<uint2*>(g_z0h + (size_t)i * 4) = uh;
        *reinterpret_cast<uint2*>(g_z0l + (size_t)i * 4) = ul;
    }
}

// ---------------- 2) fold2': (sum of fold1 partials) @ comb_w ---------------
__global__ void __launch_bounds__(256)
k_fold2(const int* __restrict__ he, int nnz,
        const float* __restrict__ Bmat, const float* __restrict__ lin_b,
        const float* __restrict__ pW1, const float* __restrict__ pb1,
        float* __restrict__ partW, float* __restrict__ partb) {
    constexpr int BM = 64, BN = 64, BK = 16, TM = 4, TN = 4;
    __shared__ __align__(16) float As[2][BK][BM + 4];
    __shared__ __align__(16) float Bs[2][BK][BN + 4];
    __shared__ float vsm[KLEN];
    __shared__ float M2s[Ec][Ec];
    __shared__ float degn[Ec];
    __shared__ float dege[MAXEDGE];
    __shared__ float Dinv[Ec];
    __shared__ float Binv[MAXEDGE];
    __shared__ float s2s;

    const int t = threadIdx.x;
    const int brow = blockIdx.y * BM;
    const int bcol = blockIdx.x * BN;
    const int kz   = blockIdx.z;
    const int kbase = kz * KLEN;
    const int tcol = (t % (BN / TN)) * TN;
    const int trow = (t / (BN / TN)) * TM;
    const int ar = t / (BK / 4);
    const int ac = (t % (BK / 4)) * 4;
    const int br = t / (BN / 4);
    const int bc = (t % (BN / 4)) * 4;

    if (blockIdx.y == 0) {
        const int* node = he;
        const int* edge = he + nnz;
        if (t < Ec) degn[t] = 0.f;
        for (int e = t; e < MAXEDGE; e += 256) dege[e] = 0.f;
        if (t < Ec * Ec) ((float*)M2s)[t] = 0.f;
        __syncthreads();
        for (int i = t; i < nnz; i += 256) {
            atomicAdd(&degn[node[i]], 1.f);
            atomicAdd(&dege[edge[i]], 1.f);
        }
        __syncthreads();
        if (t < Ec) Dinv[t] = degn[t] > 0.f ? 1.f / degn[t] : 0.f;
        for (int e = t; e < MAXEDGE; e += 256)
            Binv[e] = dege[e] > 0.f ? 1.f / dege[e] : 0.f;
        __syncthreads();
        int total = nnz * nnz;
        for (int p = t; p < total; p += 256) {
            int i = p % nnz, j = p / nnz;
            int ei = edge[i];
            if (ei == edge[j])
                atomicAdd(&M2s[node[j]][node[i]], Dinv[node[j]] * Binv[ei]);
        }
        __syncthreads();
        if (t == 0) {
            float s2 = 0.f;
            for (int u = 0; u < Ec; u++) {
                float s = 0.f;
                for (int v = 0; v < Ec; v++) s += M2s[v][u];
                s2 += s / (float)Ec;
            }
            s2s = s2;
        }
        __syncthreads();
        for (int i = t; i < KLEN; i += 256) {
            float s = ((pb1[kbase + i] + pb1[Dc + kbase + i])
                       + pb1[2 * Dc + kbase + i]) + pb1[3 * Dc + kbase + i];
            vsm[i] = s2s * s + lin_b[Dc + kbase + i];
        }
    }
    const bool bth = (blockIdx.y == 0) && (t < BN);
    float bacc = 0.f;

    unsigned long long accp[TM / 2][TN];
#pragma unroll
    for (int m = 0; m < TM / 2; m++)
#pragma unroll
        for (int n = 0; n < TN; n++) accp[m][n] = 0ull;

    float4 afrag, bfrag;
    auto ldg = [&](int k0) {
        size_t aidx = (size_t)(brow + ar) * Dc + kbase + k0 + ac;
        float4 p0 = *reinterpret_cast<const float4*>(pW1 + aidx);
        float4 p1 = *reinterpret_cast<const float4*>(pW1 + (size_t)Dc * Dc + aidx);
        float4 p2 = *reinterpret_cast<const float4*>(pW1 + 2 * (size_t)Dc * Dc + aidx);
        float4 p3 = *reinterpret_cast<const float4*>(pW1 + 3 * (size_t)Dc * Dc + aidx);
        afrag.x = ((p0.x + p1.x) + p2.x) + p3.x;
        afrag.y = ((p0.y + p1.y) + p2.y) + p3.y;
        afrag.z = ((p0.z + p1.z) + p2.z) + p3.z;
        afrag.w = ((p0.w + p1.w) + p2.w) + p3.w;
        bfrag = *reinterpret_cast<const float4*>(
            &Bmat[(size_t)(kbase + k0 + br) * Dc + bcol + bc]);
    };
    auto sts = [&](int buf) {
        As[buf][ac + 0][ar] = afrag.x;
        As[buf][ac + 1][ar] = afrag.y;
        As[buf][ac + 2][ar] = afrag.z;
        As[buf][ac + 3][ar] = afrag.w;
        *reinterpret_cast<float4*>(&Bs[buf][br][bc]) = bfrag;
    };

    ldg(0);
    sts(0);
    __syncthreads();

    int buf = 0;
    for (int k0 = 0; k0 < KLEN; k0 += BK) {
        const bool has_next = (k0 + BK) < KLEN;
        if (has_next) ldg(k0 + BK);
#pragma unroll
        for (int kk = 0; kk < BK; kk++) {
            unsigned long long rap[TM / 2];
            const unsigned long long* ap =
                reinterpret_cast<const unsigned long long*>(&As[buf][kk][trow]);
#pragma unroll
            for (int m = 0; m < TM / 2; m++) rap[m] = ap[m];
            float rb[TN];
#pragma unroll
            for (int n = 0; n < TN; n += 4)
                *reinterpret_cast<float4*>(&rb[n]) =
                    *reinterpret_cast<const float4*>(&Bs[buf][kk][tcol + n]);
            unsigned long long rbb[TN];
#pragma unroll
            for (int n = 0; n < TN; n++) rbb[n] = bcast2(rb[n]);
#pragma unroll
            for (int m = 0; m < TM / 2; m++)
#pragma unroll
                for (int n = 0; n < TN; n++) fma2(accp[m][n], rap[m], rbb[n]);
        }
        if (bth) {
#pragma unroll 4
            for (int kk = 0; kk < BK; kk++)
                bacc = fmaf(vsm[k0 + kk], Bs[buf][kk][t], bacc);
        }
        if (has_next) {
            sts(buf ^ 1);
            __syncthreads();
            buf ^= 1;
        }
    }

    if (bth) partb[kz * Dc + bcol + t] = bacc;
    float* W = partW + (size_t)kz * Dc * Dc;
#pragma unroll
    for (int m = 0; m < TM / 2; m++)
#pragma unroll
        for (int n = 0; n < TN; n++) {
            float2 v = unpack2(accp[m][n]);
            W[(size_t)(brow + trow + 2 * m + 0) * Dc + bcol + tcol + n] = v.x;
            W[(size_t)(brow + trow + 2 * m + 1) * Dc + bcol + tcol + n] = v.y;
        }
}

// ---------------- 3) combine -> Wf^T split-bf16 + bf ------------------------
__global__ void k_comb2(const float* __restrict__ extra_b) {
    int i = blockIdx.x * blockDim.x + threadIdx.x;
    const float4* p = reinterpret_cast<const float4*>(g_partW2);
    constexpr int STRIDE = Dc * Dc / 4;
    float4 a = p[i], b = p[i + STRIDE], c = p[i + 2 * STRIDE], d = p[i + 3 * STRIDE];
    float r[4];
    r[0] = ((a.x + b.x) + c.x) + d.x;
    r[1] = ((a.y + b.y) + c.y) + d.y;
    r[2] = ((a.z + b.z) + c.z) + d.z;
    r[3] = ((a.w + b.w) + c.w) + d.w;
    int k = i >> 7;
    int n = (i & 127) * 4;
#pragma unroll
    for (int j = 0; j < 4; j++) {
        __nv_bfloat16 hb = __float2bfloat16(r[j]);
        __nv_bfloat16 lb = __float2bfloat16(r[j] - __bfloat162float(hb));
        g_Wfh[(size_t)(n + j) * Dc + k] = hb;
        g_Wfl[(size_t)(n + j) * Dc + k] = lb;
    }
    if (i < Dc) {
        float s = ((g_partb2[i] + g_partb2[Dc + i]) + g_partb2[2 * Dc + i])
                  + g_partb2[3 * Dc + i];
        g_bf[i] = s + extra_b[i];
    }
}

// ---------------- 4) main GEMM: mma.sync bf16-split, pipelined --------------
// 256 threads, 8 warps as 2(m) x 4(n), warp tile 64x32, BK=16.
// Register-pipelined; MMAs issued TERM-MAJOR so consecutive HMMAs hit
// different accumulators (RAW distance 16 instead of 1). Per-accumulator
// operation order unchanged -> bit-identical results.
#define MM_BK   16
#define MM_LDK  24                      // padded row -> 48B, ldmatrix conflict-free
#define MM_TILE (128 * MM_LDK)
#define MM_BUF  (4 * MM_TILE)           // Ah, Al, Bh, Bl
#define MM_SMEM (2 * MM_BUF * 2)        // 49152 bytes

__device__ __forceinline__ void mma16816(float* c, uint32_t a0, uint32_t a1,
                                         uint32_t a2, uint32_t a3,
                                         uint32_t b0, uint32_t b1) {
    asm volatile(
        "mma.sync.aligned.m16n8k16.row.col.f32.bf16.bf16.f32 "
        "{%0,%1,%2,%3}, {%4,%5,%6,%7}, {%8,%9}, {%0,%1,%2,%3};"
        : "+f"(c[0]), "+f"(c[1]), "+f"(c[2]), "+f"(c[3])
        : "r"(a0), "r"(a1), "r"(a2), "r"(a3), "r"(b0), "r"(b1));
}

__device__ __forceinline__ void ldm_x4(uint32_t& r0, uint32_t& r1,
                                       uint32_t& r2, uint32_t& r3, uint32_t addr) {
    asm volatile(
        "ldmatrix.sync.aligned.m8n8.x4.shared.b16 {%0,%1,%2,%3}, [%4];"
        : "=r"(r0), "=r"(r1), "=r"(r2), "=r"(r3) : "r"(addr));
}

__global__ void __launch_bounds__(256, 1) k_main_mma() {
    extern __shared__ __nv_bfloat16 sm[];
    const int tid  = threadIdx.x;
    const int lane = tid & 31;
    const int wid  = tid >> 5;          // 0..7
    const int wm   = wid >> 2;          // 0..1 -> m offset wm*64
    const int wn   = wid & 3;           // 0..3 -> n offset wn*32
    const int brow = blockIdx.y * 128;
    const int bcol = blockIdx.x * 128;
    const int g    = lane >> 2;
    const int tg   = lane & 3;

    // staging: 256 threads, 1 uint4 (16B) per tile per thread
    const int r0 = tid >> 1, c0 = (tid & 1) * 8;

    // ldmatrix lane address components
    const int sel = lane >> 3;
    const int rim = lane & 7;
    const int a_row = (sel & 1) * 8 + rim;
    const int a_k   = (sel >> 1) * 8;
    const int b_row = (sel >> 1) * 8 + rim;
    const int b_k   = (sel & 1) * 8;

    float acc[4][4][4];
#pragma unroll
    for (int mf = 0; mf < 4; mf++)
#pragma unroll
        for (int nf = 0; nf < 4; nf++)
#pragma unroll
            for (int q = 0; q < 4; q++) acc[mf][nf][q] = 0.f;

    uint4 pf[4];
    auto ldg = [&](int kb) {
        pf[0] = *(const uint4*)(g_z0h + (size_t)(brow + r0) * Dc + kb + c0);
        pf[1] = *(const uint4*)(g_z0l + (size_t)(brow + r0) * Dc + kb + c0);
        pf[2] = *(const uint4*)(g_Wfh + (size_t)(bcol + r0) * Dc + kb + c0);
        pf[3] = *(const uint4*)(g_Wfl + (size_t)(bcol + r0) * Dc + kb + c0);
    };
    auto sts = [&](int buf) {
        __nv_bfloat16* base = sm + buf * MM_BUF + r0 * MM_LDK + c0;
#pragma unroll
        for (int a = 0; a < 4; a++)
            *(uint4*)(base + a * MM_TILE) = pf[a];
    };

    uint32_t Ah0[4][4], Al0[4][4], Bh0[4][2], Bl0[4][2];
    uint32_t Ah1[4][4], Al1[4][4], Bh1[4][2], Bl1[4][2];

#define LOADF(AH, AL, BH, BL, bidx) do {                                       \
    const __nv_bfloat16* base_ = sm + (bidx) * MM_BUF;                         \
    _Pragma("unroll")                                                          \
    for (int mf = 0; mf < 4; mf++) {                                           \
        uint32_t a1_ = (uint32_t)__cvta_generic_to_shared(                     \
            base_ + 0 * MM_TILE + (wm * 64 + mf * 16 + a_row) * MM_LDK + a_k); \
        ldm_x4(AH[mf][0], AH[mf][1], AH[mf][2], AH[mf][3], a1_);               \
        uint32_t a2_ = (uint32_t)__cvta_generic_to_shared(                     \
            base_ + 1 * MM_TILE + (wm * 64 + mf * 16 + a_row) * MM_LDK + a_k); \
        ldm_x4(AL[mf][0], AL[mf][1], AL[mf][2], AL[mf][3], a2_);               \
    }                                                                          \
    _Pragma("unroll")                                                          \
    for (int nf2 = 0; nf2 < 2; nf2++) {                                        \
        uint32_t b1_ = (uint32_t)__cvta_generic_to_shared(                     \
            base_ + 2 * MM_TILE + (wn * 32 + nf2 * 16 + b_row) * MM_LDK + b_k);\
        ldm_x4(BH[nf2 * 2][0], BH[nf2 * 2][1],                                 \
               BH[nf2 * 2 + 1][0], BH[nf2 * 2 + 1][1], b1_);                   \
        uint32_t b2_ = (uint32_t)__cvta_generic_to_shared(                     \
            base_ + 3 * MM_TILE + (wn * 32 + nf2 * 16 + b_row) * MM_LDK + b_k);\
        ldm_x4(BL[nf2 * 2][0], BL[nf2 * 2][1],                                 \
               BL[nf2 * 2 + 1][0], BL[nf2 * 2 + 1][1], b2_);                   \
    }                                                                          \
} while (0)

// TERM-MAJOR: all AhBh, then all AhBl, then all AlBh. Consecutive HMMAs hit
// different accumulators; per-accumulator op order is unchanged (bit-exact).
#define MMAS(AH, AL, BH, BL) do {                                              \
    _Pragma("unroll")                                                          \
    for (int mf = 0; mf < 4; mf++)                                             \
    _Pragma("unroll")                                                          \
    for (int nf = 0; nf < 4; nf++)                                             \
        mma16816(acc[mf][nf], AH[mf][0], AH[mf][1], AH[mf][2], AH[mf][3],      \
                 BH[nf][0], BH[nf][1]);                                        \
    _Pragma("unroll")                                                          \
    for (int mf = 0; mf < 4; mf++)                                             \
    _Pragma("unroll")                                                          \
    for (int nf = 0; nf < 4; nf++)                                             \
        mma16816(acc[mf][nf], AH[mf][0], AH[mf][1], AH[mf][2], AH[mf][3],      \
                 BL[nf][0], BL[nf][1]);                                        \
    _Pragma("unroll")                                                          \
    for (int mf = 0; mf < 4; mf++)                                             \
    _Pragma("unroll")                                                          \
    for (int nf = 0; nf < 4; nf++)                                             \
        mma16816(acc[mf][nf], AL[mf][0], AL[mf][1], AL[mf][2], AL[mf][3],      \
                 BH[nf][0], BH[nf][1]);                                        \
} while (0)

    // prologue: tile 0 in smem buf0 + fragments; tile 1 staged in regs
    ldg(0);
    sts(0);
    __syncthreads();
    LOADF(Ah0, Al0, Bh0, Bl0, 0);
    ldg(MM_BK);

    for (int kt = 0; kt < 32; kt += 2) {
        // stage A: smem+frags for kt+1 (buf1, set1); compute kt (set0)
        sts(1);
        __syncthreads();
        LOADF(Ah1, Al1, Bh1, Bl1, 1);
        if (kt + 2 < 32) ldg((kt + 2) * MM_BK);
        MMAS(Ah0, Al0, Bh0, Bl0);
        // stage B: smem+frags for kt+2 (buf0, set0); compute kt+1 (set1)
        if (kt + 2 < 32) {
            sts(0);
            __syncthreads();
            LOADF(Ah0, Al0, Bh0, Bl0, 0);
            if (kt + 3 < 32) ldg((kt + 3) * MM_BK);
        }
        MMAS(Ah1, Al1, Bh1, Bl1);
    }

    // epilogue: bias + exact GELU
#pragma unroll
    for (int mf = 0; mf < 4; mf++) {
#pragma unroll
        for (int nf = 0; nf < 4; nf++) {
            int mbase = brow + wm * 64 + mf * 16 + g;
            int nbase = bcol + wn * 32 + nf * 8 + tg * 2;
            float b0v = g_bf[nbase], b1v = g_bf[nbase + 1];
            float x0 = acc[mf][nf][0] + b0v;
            float x1 = acc[mf][nf][1] + b1v;
            float x2 = acc[mf][nf][2] + b0v;
            float x3 = acc[mf][nf][3] + b1v;
            float2 lo, hi;
            lo.x = 0.5f * x0 * (1.f + erff(x0 * 0.70710678118654752f));
            lo.y = 0.5f * x1 * (1.f + erff(x1 * 0.70710678118654752f));
            hi.x = 0.5f * x2 * (1.f + erff(x2 * 0.70710678118654752f));
            hi.y = 0.5f * x3 * (1.f + erff(x3 * 0.70710678118654752f));
            *reinterpret_cast<float2*>(g_y + (size_t)mbase * Dc + nbase) = lo;
            *reinterpret_cast<float2*>(g_y + (size_t)(mbase + 8) * Dc + nbase) = hi;
        }
    }
}

// ---------------- 5) LayerNorm over D=512 -----------------------------------
__global__ void k_ln(const float* __restrict__ Y, const float* __restrict__ gam,
                     const float* __restrict__ bet, float* __restrict__ out) {
    int row = blockIdx.x;
    const float* y = Y + (size_t)row * Dc;
    int t = threadIdx.x;
    float v[4];
    float s = 0.f;
#pragma unroll
    for (int i = 0; i < 4; i++) { v[i] = y[t + i * 128]; s += v[i]; }
    __shared__ float red[4];
#pragma unroll
    for (int o = 16; o; o >>= 1) s += __shfl_xor_sync(0xffffffffu, s, o);
    if ((t & 31) == 0) red[t >> 5] = s;
    __syncthreads();
    float mu = (red[0] + red[1] + red[2] + red[3]) * (1.f / Dc);
    __syncthreads();
    float d2 = 0.f;
#pragma unroll
    for (int i = 0; i < 4; i++) { float d = v[i] - mu; d2 += d * d; }
#pragma unroll
    for (int o = 16; o; o >>= 1) d2 += __shfl_xor_sync(0xffffffffu, d2, o);
    if ((t & 31) == 0) red[t >> 5] = d2;
    __syncthreads();
    float var = (red[0] + red[1] + red[2] + red[3]) * (1.f / Dc);
    float rs = rsqrtf(var + 1e-5f);
#pragma unroll
    for (int i = 0; i < 4; i++) {
        int c = t + i * 128;
        out[(size_t)row * Dc + c] = (v[i] - mu) * rs * gam[c] + bet[c];
    }
}

// ---------------- launch -----------------------------------------------------
extern "C" void kernel_launch(void* const* d_in, const int* in_sizes, int n_in,
                              void* d_out, int out_size) {
    const float* x      = (const float*)d_in[0];
    const int*   he     = (const int*)  d_in[1];
    const float* lin_w  = (const float*)d_in[2];
    const float* lin_b  = (const float*)d_in[3];
    const float* comb_w = (const float*)d_in[4];
    const float* comb_b = (const float*)d_in[5];
    const float* ln_g   = (const float*)d_in[6];
    const float* ln_b   = (const float*)d_in[7];
    float* out = (float*)d_out;
    const int nnz = in_sizes[1] / 2;

    float *p_y, *p_partW, *p_partb, *p_partW2, *p_partb2;
    cudaGetSymbolAddress((void**)&p_y,      g_y);
    cudaGetSymbolAddress((void**)&p_partW,  g_partW);
    cudaGetSymbolAddress((void**)&p_partb,  g_partb);
    cudaGetSymbolAddress((void**)&p_partW2, g_partW2);
    cudaGetSymbolAddress((void**)&p_partb2, g_partb2);

    cudaFuncSetAttribute(k_main_mma,
                         cudaFuncAttributeMaxDynamicSharedMemorySize, MM_SMEM);

    // 1) fused: fold1 (blocks 0-255) + weighted expert reduce (blocks 256-2303)
    {
        int grid = FOLD_BLOCKS + Gc * (Dc / 4) / 256;   // 256 + 2048
        k_red_fold<<<grid, 256>>>(x, he, nnz, lin_w, lin_w + Dc * Dc, lin_b,
                                  p_partW, p_partb);
    }

    // 2) fold2': (sum partW) @ comb_w ; bias GEMV on inline-computed b1f
    {
        dim3 grid(Dc / 64, Dc / 64, KZ);
        k_fold2<<<grid, 256>>>(he, nnz, comb_w, lin_b, p_partW, p_partb,
                               p_partW2, p_partb2);
    }

    // 3) combine -> Wf^T split-bf16 + bf
    k_comb2<<<Dc * Dc / 4 / 256, 256>>>(comb_b);

    // 4) main GEMM (mma.sync, ldmatrix, term-major pipelined)
    {
        dim3 grid(Dc / 128, Gc / 128);   // (4, 32) = 128 CTAs = 1 wave
        k_main_mma<<<grid, 256, MM_SMEM>>>();
    }

    // 5) LayerNorm -> output
    k_ln<<<Gc, 128>>>(p_y, ln_g, ln_b, out);
}